// round 14
// baseline (speedup 1.0000x reference)
#include <cuda_runtime.h>
#include <math.h>

#define NTOK (128*1024)   // B=128, S=1024
typedef unsigned long long u64;
typedef unsigned int u32;

// ---------------- device scratch (static: no cudaMalloc allowed) ----------
__device__ __align__(128) float g_xn[(size_t)NTOK*64];
__device__ __align__(128) float g_xp[(size_t)NTOK*384];   // xp -> f0
__device__ __align__(128) float g_gru[(size_t)NTOK*128];

// ---------------- f32x2 helpers ---------------------------------------------
__device__ __forceinline__ u64 pk(float lo, float hi){
  u64 r; asm("mov.b64 %0,{%1,%2};" : "=l"(r) : "f"(lo), "f"(hi)); return r;
}
__device__ __forceinline__ void upk(u64 a, float& lo, float& hi){
  asm("mov.b64 {%0,%1},%2;" : "=f"(lo), "=f"(hi) : "l"(a));
}
__device__ __forceinline__ void fma2(u64& d, u64 a, u64 b){
  asm("fma.rn.f32x2 %0,%1,%2,%0;" : "+l"(d) : "l"(a), "l"(b));
}
__device__ __forceinline__ u64 add2(u64 a, u64 b){
  u64 r; asm("add.rn.f32x2 %0,%1,%2;" : "=l"(r) : "l"(a), "l"(b)); return r;
}
__device__ __forceinline__ float f2s(u64 a){
  float lo,hi; upk(a,lo,hi); return lo+hi;
}
__device__ __forceinline__ float lk(float x){ return fmaxf(x, 0.01f*x); }
__device__ __forceinline__ float sgm(float x){ return 1.0f/(1.0f+__expf(-x)); }

// ---------------- tf32 mma helpers ------------------------------------------
__device__ __forceinline__ u32 tf32c(float f){
  u32 r; asm("cvt.rna.tf32.f32 %0,%1;" : "=r"(r) : "f"(f)); return r;
}
__device__ __forceinline__ void tf32s(float f, u32& hi, u32& lo){
  hi = tf32c(f);
  lo = tf32c(f - __uint_as_float(hi));
}
__device__ __forceinline__ void mma8(float* d, const u32* a, const u32* b){
  asm("mma.sync.aligned.m16n8k8.row.col.f32.tf32.tf32.f32 "
      "{%0,%1,%2,%3},{%4,%5,%6,%7},{%8,%9},{%0,%1,%2,%3};"
      : "+f"(d[0]),"+f"(d[1]),"+f"(d[2]),"+f"(d[3])
      : "r"(a[0]),"r"(a[1]),"r"(a[2]),"r"(a[3]),"r"(b[0]),"r"(b[1]));
}

// packed dot products (k_front)
__device__ __forceinline__ float dot32p(const u64* __restrict__ w, const u64 (&x)[16]){
  u64 a0=0,a1=0,a2=0,a3=0;
  const ulonglong2* w2=(const ulonglong2*)w;
#pragma unroll
  for(int k=0;k<4;k++){
    ulonglong2 v0=w2[2*k], v1=w2[2*k+1];
    fma2(a0,v0.x,x[4*k]);   fma2(a1,v0.y,x[4*k+1]);
    fma2(a2,v1.x,x[4*k+2]); fma2(a3,v1.y,x[4*k+3]);
  }
  return f2s(add2(add2(a0,a1),add2(a2,a3)));
}
__device__ __forceinline__ float dot64p(const u64* __restrict__ w, const u64 (&x)[32]){
  u64 a0=0,a1=0,a2=0,a3=0;
  const ulonglong2* w2=(const ulonglong2*)w;
#pragma unroll
  for(int k=0;k<8;k++){
    ulonglong2 v0=w2[2*k], v1=w2[2*k+1];
    fma2(a0,v0.x,x[4*k]);   fma2(a1,v0.y,x[4*k+1]);
    fma2(a2,v1.x,x[4*k+2]); fma2(a3,v1.y,x[4*k+3]);
  }
  return f2s(add2(add2(a0,a1),add2(a2,a3)));
}

// -------- kernel 1 SMEM layout (R6/R9, known-good) ---------------------------
#define OF_MEW1 0
#define OF_MEB1 96
#define OF_MEW2 128
#define OF_MEB2 2176
#define OF_AEW1 2240
#define OF_AEB1 2432
#define OF_AEW2 2464
#define OF_AEB2 4512
#define OF_INW  4576
#define OF_INB  16864
#define OF_WO   17056
#define OF_WOB  21152
#define OF_LNG  21216
#define OF_LNB  21280
#define OF_WTOT 21344
#define OF_BUFA (OF_WTOT)
#define OF_BUFB (OF_WTOT+8192)
#define OF_BUFC (OF_WTOT+16384)
#define OF_BUFD (OF_WTOT+24576)
#define SM1_FLOATS (OF_WTOT+32768)
#define SM1_BYTES  (SM1_FLOATS*4)

__device__ __forceinline__ void enc_m(const float* __restrict__ sm,
                                      u64* __restrict__ buf, int tid,
                                      float x0, float x1, float x2){
  u64 hp[16];
#pragma unroll
  for(int j=0;j<32;j+=2){
    float a0 = sm[OF_MEB1+j]   + sm[OF_MEW1+j*3+0]*x0 + sm[OF_MEW1+j*3+1]*x1 + sm[OF_MEW1+j*3+2]*x2;
    float a1 = sm[OF_MEB1+j+1] + sm[OF_MEW1+j*3+3]*x0 + sm[OF_MEW1+j*3+4]*x1 + sm[OF_MEW1+j*3+5]*x2;
    hp[j>>1]=pk(lk(a0),lk(a1));
  }
#pragma unroll 1
  for(int o=0;o<64;o+=2){
    float y0 = sm[OF_MEB2+o]   + dot32p((const u64*)(sm+OF_MEW2+o*32),hp);
    float y1 = sm[OF_MEB2+o+1] + dot32p((const u64*)(sm+OF_MEW2+(o+1)*32),hp);
    buf[(o>>1)*128+tid]=pk(y0,y1);
  }
}

// ------------- kernel 1: encoders + attention + residual + LayerNorm -------
__global__ void __launch_bounds__(128) k_front(
  const float* __restrict__ obs,
  const float* __restrict__ me_w1, const float* __restrict__ me_b1,
  const float* __restrict__ me_w2, const float* __restrict__ me_b2,
  const float* __restrict__ ae_w1, const float* __restrict__ ae_b1,
  const float* __restrict__ ae_w2, const float* __restrict__ ae_b2,
  const float* __restrict__ in_w,  const float* __restrict__ in_b,
  const float* __restrict__ wo,    const float* __restrict__ wob,
  const float* __restrict__ lng,   const float* __restrict__ lnb,
  float* __restrict__ xn_out)
{
  extern __shared__ __align__(16) float sm[];
  const int tid=threadIdx.x;
  {
    const float* srcs[14]={me_w1,me_b1,me_w2,me_b2,ae_w1,ae_b1,ae_w2,ae_b2,in_w,in_b,wo,wob,lng,lnb};
    const int offs[14]={OF_MEW1,OF_MEB1,OF_MEW2,OF_MEB2,OF_AEW1,OF_AEB1,OF_AEW2,OF_AEB2,OF_INW,OF_INB,OF_WO,OF_WOB,OF_LNG,OF_LNB};
    const int lens[14]={96,32,2048,64,192,32,2048,64,12288,192,4096,64,64,64};
    for(int a=0;a<14;a++)
      for(int i=tid;i<lens[a];i+=128) sm[offs[a]+i]=srcs[a][i];
  }
  __syncthreads();
  u64* bA=(u64*)(sm+OF_BUFA);
  u64* bB=(u64*)(sm+OF_BUFB);
  u64* bC=(u64*)(sm+OF_BUFC);
  u64* bD=(u64*)(sm+OF_BUFD);

  const size_t tok=(size_t)blockIdx.x*128+tid;
  float ob[12];
  {
    const float4* p=(const float4*)(obs+tok*12);
    float4 v0=p[0],v1=p[1],v2=p[2];
    ob[0]=v0.x; ob[1]=v0.y; ob[2]=v0.z; ob[3]=v0.w;
    ob[4]=v1.x; ob[5]=v1.y; ob[6]=v1.z; ob[7]=v1.w;
    ob[8]=v2.x; ob[9]=v2.y; ob[10]=v2.z; ob[11]=v2.w;
  }

  // ---- ace -> bA
  {
    u64 hp[16];
#pragma unroll
    for(int j=0;j<32;j+=2){
      float a0=sm[OF_AEB1+j], a1=sm[OF_AEB1+j+1];
#pragma unroll
      for(int i=0;i<6;i++){ a0+=sm[OF_AEW1+j*6+i]*ob[6+i]; a1+=sm[OF_AEW1+(j+1)*6+i]*ob[6+i]; }
      hp[j>>1]=pk(lk(a0),lk(a1));
    }
#pragma unroll 1
    for(int o=0;o<64;o+=2){
      float y0=sm[OF_AEB2+o]  +dot32p((const u64*)(sm+OF_AEW2+o*32),hp);
      float y1=sm[OF_AEB2+o+1]+dot32p((const u64*)(sm+OF_AEW2+(o+1)*32),hp);
      bA[(o>>1)*128+tid]=pk(y0,y1);
    }
  }
  // ---- q = Wq@ace + bq -> bB
  {
    u64 ar[32];
#pragma unroll
    for(int k=0;k<32;k++) ar[k]=bA[k*128+tid];
#pragma unroll 1
    for(int o=0;o<64;o+=2){
      float y0=sm[OF_INB+o]  +dot64p((const u64*)(sm+OF_INW+(size_t)o*64),ar);
      float y1=sm[OF_INB+o+1]+dot64p((const u64*)(sm+OF_INW+(size_t)(o+1)*64),ar);
      bB[(o>>1)*128+tid]=pk(y0,y1);
    }
  }
  enc_m(sm,bC,tid,ob[0],ob[1],ob[2]);
  enc_m(sm,bD,tid,ob[3],ob[4],ob[5]);

  float a0h[4];
  {
    u64 er[32];
#pragma unroll
    for(int k=0;k<32;k++) er[k]=bC[k*128+tid];
    float s0[4];
#pragma unroll
    for(int h=0;h<4;h++){
      float acc=0.f;
#pragma unroll 1
      for(int oo=0;oo<16;oo+=2){ int o=h*16+oo;
        float q0,q1; upk(bB[(o>>1)*128+tid],q0,q1);
        float k0=sm[OF_INB+64+o]  +dot64p((const u64*)(sm+OF_INW+(size_t)(64+o)*64),er);
        float k1=sm[OF_INB+64+o+1]+dot64p((const u64*)(sm+OF_INW+(size_t)(65+o)*64),er);
        acc+=q0*k0+q1*k1;
      }
      s0[h]=acc;
    }
#pragma unroll
    for(int k=0;k<32;k++) er[k]=bD[k*128+tid];
#pragma unroll
    for(int h=0;h<4;h++){
      float acc=0.f;
#pragma unroll 1
      for(int oo=0;oo<16;oo+=2){ int o=h*16+oo;
        float q0,q1; upk(bB[(o>>1)*128+tid],q0,q1);
        float k0=sm[OF_INB+64+o]  +dot64p((const u64*)(sm+OF_INW+(size_t)(64+o)*64),er);
        float k1=sm[OF_INB+64+o+1]+dot64p((const u64*)(sm+OF_INW+(size_t)(65+o)*64),er);
        acc+=q0*k0+q1*k1;
      }
      a0h[h]=sgm((s0[h]-acc)*0.25f);
    }
  }
  {
    u64 m1r[32], m2r[32];
#pragma unroll
    for(int k=0;k<32;k++){ m1r[k]=bC[k*128+tid]; m2r[k]=bD[k*128+tid]; }
#pragma unroll
    for(int h=0;h<4;h++){
      float a0=a0h[h], a1=1.0f-a0h[h];
#pragma unroll 1
      for(int oo=0;oo<16;oo+=2){ int o=h*16+oo;
        const u64* r0=(const u64*)(sm+OF_INW+(size_t)(128+o)*64);
        const u64* r1=(const u64*)(sm+OF_INW+(size_t)(129+o)*64);
        float y0=sm[OF_INB+128+o]  +a0*dot64p(r0,m1r)+a1*dot64p(r0,m2r);
        float y1=sm[OF_INB+128+o+1]+a0*dot64p(r1,m1r)+a1*dot64p(r1,m2r);
        bB[(o>>1)*128+tid]=pk(y0,y1);
      }
    }
  }
  float mu,rs;
  {
    u64 cr[32];
#pragma unroll
    for(int k=0;k<32;k++) cr[k]=bB[k*128+tid];
    float sum=0.f,sq=0.f;
#pragma unroll 1
    for(int o=0;o<64;o+=2){
      float a0v,a1v; upk(bA[(o>>1)*128+tid],a0v,a1v);
      float x0=sm[OF_WOB+o]  +dot64p((const u64*)(sm+OF_WO+(size_t)o*64),cr)+a0v;
      float x1=sm[OF_WOB+o+1]+dot64p((const u64*)(sm+OF_WO+(size_t)(o+1)*64),cr)+a1v;
      bC[(o>>1)*128+tid]=pk(x0,x1);
      sum+=x0+x1; sq+=x0*x0+x1*x1;
    }
    mu=sum*(1.0f/64.0f);
    float var=sq*(1.0f/64.0f)-mu*mu;
    rs=rsqrtf(var+1e-5f);
  }
  float* op = xn_out + tok*64;
#pragma unroll 1
  for(int o=0;o<64;o+=4){
    float x0,x1,x2,x3;
    upk(bC[(o>>1)*128+tid],x0,x1);
    upk(bC[((o>>1)+1)*128+tid],x2,x3);
    float4 v;
    v.x=(x0-mu)*rs*sm[OF_LNG+o+0]+sm[OF_LNB+o+0];
    v.y=(x1-mu)*rs*sm[OF_LNG+o+1]+sm[OF_LNB+o+1];
    v.z=(x2-mu)*rs*sm[OF_LNG+o+2]+sm[OF_LNB+o+2];
    v.w=(x3-mu)*rs*sm[OF_LNG+o+3]+sm[OF_LNB+o+3];
    *(float4*)(op+o)=v;
  }
}

// ============== kernel 2: xp GEMM (persistent split-tf32, R9-proven) ========
#define XPAD 68
#define SM2_WORDS (43520+192)
#define SM2_BYTES (SM2_WORDS*4)
__global__ void __launch_bounds__(256,1) k_xpP(
  const float* __restrict__ xn, const float* __restrict__ w_ih,
  const float* __restrict__ b_ih, float* __restrict__ xp)
{
  extern __shared__ __align__(16) u32 smw[];
  u32* Whi = smw;
  u32* Wlo = smw + 13056;
  u32* Xhi = smw + 26112;
  u32* Xlo = smw + 34816;
  float* bs = (float*)(smw + 43520);
  const int tid = threadIdx.x;
  const int oh = blockIdx.y;
  for(int i=tid;i<12288;i+=256){
    int n=i>>6, k=i&63;
    u32 hi,lo; tf32s(w_ih[(size_t)(oh*192+n)*64+k],hi,lo);
    Whi[n*XPAD+k]=hi; Wlo[n*XPAD+k]=lo;
  }
  for(int i=tid;i<192;i+=256) bs[i]=b_ih[oh*192+i];

  const int lane=tid&31, gid=lane>>2, tig=lane&3;
  const int w=tid>>5, tokblk=w>>1, ob=w&1;

#pragma unroll 1
  for(int t=blockIdx.x; t<1024; t+=74){
    const size_t tok0=(size_t)t*128;
    __syncthreads();
    for(int i=tid;i<8192;i+=256){
      int tt=i>>6, k=i&63;
      u32 hi,lo; tf32s(xn[tok0*64+i],hi,lo);
      Xhi[tt*XPAD+k]=hi; Xlo[tt*XPAD+k]=lo;
    }
    __syncthreads();

    float d[2][12][4];
#pragma unroll
    for(int m=0;m<2;m++)
#pragma unroll
      for(int n=0;n<12;n++)
#pragma unroll
        for(int r=0;r<4;r++) d[m][n][r]=0.f;

#pragma unroll
    for(int ks=0;ks<8;ks++){
      u32 ah0[4],al0[4],ah1[4],al1[4];
      {
        const u32* p;
        p = Xhi + (tokblk*32+gid)*XPAD + ks*8 + tig;
        ah0[0]=p[0]; ah0[1]=p[8*XPAD]; ah0[2]=p[4]; ah0[3]=p[8*XPAD+4];
        p = Xlo + (tokblk*32+gid)*XPAD + ks*8 + tig;
        al0[0]=p[0]; al0[1]=p[8*XPAD]; al0[2]=p[4]; al0[3]=p[8*XPAD+4];
        p = Xhi + (tokblk*32+16+gid)*XPAD + ks*8 + tig;
        ah1[0]=p[0]; ah1[1]=p[8*XPAD]; ah1[2]=p[4]; ah1[3]=p[8*XPAD+4];
        p = Xlo + (tokblk*32+16+gid)*XPAD + ks*8 + tig;
        al1[0]=p[0]; al1[1]=p[8*XPAD]; al1[2]=p[4]; al1[3]=p[8*XPAD+4];
      }
#pragma unroll
      for(int n=0;n<12;n++){
        const u32* bh = Whi + (ob*96+n*8+gid)*XPAD + ks*8 + tig;
        u32 bhf[2]={bh[0],bh[4]};
        const u32* bl = Wlo + (ob*96+n*8+gid)*XPAD + ks*8 + tig;
        u32 blf[2]={bl[0],bl[4]};
        mma8(d[0][n],ah0,bhf); mma8(d[0][n],al0,bhf); mma8(d[0][n],ah0,blf);
        mma8(d[1][n],ah1,bhf); mma8(d[1][n],al1,bhf); mma8(d[1][n],ah1,blf);
      }
    }
#pragma unroll
    for(int m=0;m<2;m++){
      int row = tokblk*32+m*16+gid;
#pragma unroll
      for(int n=0;n<12;n++){
        int lc = ob*96+n*8+tig*2;
        int gc = oh*192+lc;
        float2 v0 = make_float2(d[m][n][0]+bs[lc], d[m][n][1]+bs[lc+1]);
        float2 v1 = make_float2(d[m][n][2]+bs[lc], d[m][n][3]+bs[lc+1]);
        *(float2*)(xp + (tok0+row)*384 + gc)   = v0;
        *(float2*)(xp + (tok0+row+8)*384 + gc) = v1;
      }
    }
  }
}

// ============== kernel 3: GRU scan (768 thr, K-split 2-way) =================
__global__ void __launch_bounds__(768,1) k_gru(
  const float* __restrict__ xp, const float* __restrict__ h0,
  const float* __restrict__ w_hh, const float* __restrict__ b_hh,
  float* __restrict__ gru_out, float* __restrict__ out)
{
  __shared__ __align__(16) float hs[128];
  __shared__ float sr[128], sz[128], sxg[128], shg[128];
  const int tid=threadIdx.x, b=blockIdx.x;
  const int w=tid>>5, l=tid&31;
  const int j = w*16 + (l&15);     // output row 0..383 (each row on 2 lanes)
  const int kh = l>>4;             // K-half: 0 -> k[0..63], 1 -> k[64..127]
  u64 w2[32];                      // 64 floats = this thread's half-row
  {
    const ulonglong2* wr=(const ulonglong2*)(w_hh+(size_t)j*128 + kh*64);
#pragma unroll
    for(int k=0;k<16;k++){ ulonglong2 v=wr[k]; w2[2*k]=v.x; w2[2*k+1]=v.y; }
  }
  const float bj=b_hh[j];
  if(tid<128) hs[tid]=h0[b*128+tid];
  __syncthreads();
  const float* xbase = xp + (size_t)b*1024*384 + j;
  float* gbase = gru_out + (size_t)b*1024*128;
  const int i = j & 127;
  float xt = xbase[0];
#pragma unroll 1
  for(int t=0;t<1024;t++){
    float xt_n = (t<1023) ? xbase[(size_t)(t+1)*384] : 0.f;   // prefetch
    const ulonglong2* h2=(const ulonglong2*)(hs + kh*64);     // 64 floats = 16 ull2
    u64 a0=0,a1=0,a2=0,a3=0;
#pragma unroll
    for(int k=0;k<8;k++){
      ulonglong2 v0=h2[2*k], v1=h2[2*k+1];
      fma2(a0,w2[4*k],v0.x);   fma2(a1,w2[4*k+1],v0.y);
      fma2(a2,w2[4*k+2],v1.x); fma2(a3,w2[4*k+3],v1.y);
    }
    float part=f2s(add2(add2(a0,a1),add2(a2,a3)));
    float acc = part + __shfl_xor_sync(0xFFFFFFFFu, part, 16);
    if(l<16){
      if(j<128)       sr[i]=xt+bj+acc;
      else if(j<256)  sz[i]=xt+bj+acc;
      else          { shg[i]=bj+acc; sxg[i]=xt; }
    }
    __syncthreads();
    if(tid<128){
      float r=sgm(sr[tid]);
      float z=sgm(sz[tid]);
      float g=tanhf(sxg[tid]+r*shg[tid]);
      float hn=z*(hs[tid]-g)+g;           // (1-z)*g + z*h
      gbase[(size_t)t*128+tid]=hn;
      hs[tid]=hn;
    }
    __syncthreads();
    xt = xt_n;
  }
  if(tid<128) out[(size_t)NTOK + (size_t)b*128 + tid] = hs[tid];
}

// ============== kernel 4a: MLP layer 0 (persistent, R9-proven) ==============
#define MPAD 132
#define SML0_WORDS (50688+128)
#define SML0_BYTES (SML0_WORDS*4)
__global__ void __launch_bounds__(256,1) k_l0P(
  const float* __restrict__ gin,
  const float* __restrict__ w0, const float* __restrict__ b0,
  float* __restrict__ f0)
{
  extern __shared__ __align__(16) u32 smw[];
  u32* Whi = smw;
  u32* Wlo = smw + 16896;
  u32* Xhi = smw + 33792;
  u32* Xlo = smw + 42240;
  float* b0s = (float*)(smw + 50688);
  const int tid = threadIdx.x;
  for(int i=tid;i<16384;i+=256){
    int n=i>>7, k=i&127;
    u32 hi,lo; tf32s(w0[i],hi,lo);
    Whi[n*MPAD+k]=hi; Wlo[n*MPAD+k]=lo;
  }
  if(tid<128) b0s[tid]=b0[tid];

  const int lane=tid&31, gid=lane>>2, tig=lane&3;
  const int w=tid>>5, mt=w&3, ob=w>>2;

#pragma unroll 1
  for(int t=blockIdx.x; t<2048; t+=148){
    const size_t tok0=(size_t)t*64;
    __syncthreads();
    for(int i=tid;i<8192;i+=256){
      int tt=i>>7, k=i&127;
      u32 hi,lo; tf32s(gin[tok0*128+i],hi,lo);
      Xhi[tt*MPAD+k]=hi; Xlo[tt*MPAD+k]=lo;
    }
    __syncthreads();

    float d[8][4];
#pragma unroll
    for(int n=0;n<8;n++){ d[n][0]=0;d[n][1]=0;d[n][2]=0;d[n][3]=0; }
#pragma unroll
    for(int ks=0;ks<16;ks++){
      const u32* ph = Xhi + (mt*16+gid)*MPAD + ks*8 + tig;
      u32 ah[4]={ph[0], ph[8*MPAD], ph[4], ph[8*MPAD+4]};
      const u32* pl = Xlo + (mt*16+gid)*MPAD + ks*8 + tig;
      u32 al[4]={pl[0], pl[8*MPAD], pl[4], pl[8*MPAD+4]};
#pragma unroll
      for(int n=0;n<8;n++){
        const u32* bh = Whi + (ob*64+n*8+gid)*MPAD + ks*8 + tig;
        u32 bhf[2]={bh[0],bh[4]};
        const u32* bl = Wlo + (ob*64+n*8+gid)*MPAD + ks*8 + tig;
        u32 blf[2]={bl[0],bl[4]};
        mma8(d[n],ah,bhf); mma8(d[n],al,bhf); mma8(d[n],ah,blf);
      }
    }
    int row = mt*16+gid;
#pragma unroll
    for(int n=0;n<8;n++){
      int col = ob*64+n*8+tig*2;
      float2 v0 = make_float2(lk(d[n][0]+b0s[col]), lk(d[n][1]+b0s[col+1]));
      float2 v1 = make_float2(lk(d[n][2]+b0s[col]), lk(d[n][3]+b0s[col+1]));
      *(float2*)(f0 + (tok0+row)*128 + col)   = v0;
      *(float2*)(f0 + (tok0+row+8)*128 + col) = v1;
    }
  }
}

// ============== kernel 4b: MLP layer 1 + value head (persistent, R9) ========
#define SML1_WORDS (50944+128)
#define SML1_BYTES (SML1_WORDS*4)
__global__ void __launch_bounds__(256,1) k_l1P(
  const float* __restrict__ f0in,
  const float* __restrict__ w1, const float* __restrict__ b1,
  const float* __restrict__ ow, const float* __restrict__ obias,
  float* __restrict__ out)
{
  extern __shared__ __align__(16) u32 smw[];
  u32* Whi = smw;
  u32* Wlo = smw + 16896;
  u32* Xhi = smw + 33792;
  u32* Xlo = smw + 42240;
  float* b1s = (float*)(smw + 50688);
  float* ows = (float*)(smw + 50816);
  float* ppart = (float*)(smw + 50944);
  const int tid = threadIdx.x;
  for(int i=tid;i<16384;i+=256){
    int n=i>>7, k=i&127;
    u32 hi,lo; tf32s(w1[i],hi,lo);
    Whi[n*MPAD+k]=hi; Wlo[n*MPAD+k]=lo;
  }
  if(tid<128){ b1s[tid]=b1[tid]; ows[tid]=ow[tid]; }
  const float obv = obias[0];

  const int lane=tid&31, gid=lane>>2, tig=lane&3;
  const int w=tid>>5, mt=w&3, ob=w>>2;

#pragma unroll 1
  for(int t=blockIdx.x; t<2048; t+=148){
    const size_t tok0=(size_t)t*64;
    __syncthreads();
    for(int i=tid;i<8192;i+=256){
      int tt=i>>7, k=i&127;
      u32 hi,lo; tf32s(f0in[tok0*128+i],hi,lo);
      Xhi[tt*MPAD+k]=hi; Xlo[tt*MPAD+k]=lo;
    }
    __syncthreads();

    float d[8][4];
#pragma unroll
    for(int n=0;n<8;n++){ d[n][0]=0;d[n][1]=0;d[n][2]=0;d[n][3]=0; }
#pragma unroll
    for(int ks=0;ks<16;ks++){
      const u32* ph = Xhi + (mt*16+gid)*MPAD + ks*8 + tig;
      u32 ah[4]={ph[0], ph[8*MPAD], ph[4], ph[8*MPAD+4]};
      const u32* pl = Xlo + (mt*16+gid)*MPAD + ks*8 + tig;
      u32 al[4]={pl[0], pl[8*MPAD], pl[4], pl[8*MPAD+4]};
#pragma unroll
      for(int n=0;n<8;n++){
        const u32* bh = Whi + (ob*64+n*8+gid)*MPAD + ks*8 + tig;
        u32 bhf[2]={bh[0],bh[4]};
        const u32* bl = Wlo + (ob*64+n*8+gid)*MPAD + ks*8 + tig;
        u32 blf[2]={bl[0],bl[4]};
        mma8(d[n],ah,bhf); mma8(d[n],al,bhf); mma8(d[n],ah,blf);
      }
    }
    float pA=0.f, pB=0.f;
#pragma unroll
    for(int n=0;n<8;n++){
      int col = ob*64+n*8+tig*2;
      pA += ows[col]*lk(d[n][0]+b1s[col]) + ows[col+1]*lk(d[n][1]+b1s[col+1]);
      pB += ows[col]*lk(d[n][2]+b1s[col]) + ows[col+1]*lk(d[n][3]+b1s[col+1]);
    }
    pA += __shfl_xor_sync(0xFFFFFFFF,pA,1); pA += __shfl_xor_sync(0xFFFFFFFF,pA,2);
    pB += __shfl_xor_sync(0xFFFFFFFF,pB,1); pB += __shfl_xor_sync(0xFFFFFFFF,pB,2);
    if(tig==0){
      ppart[ob*64 + mt*16 + gid]     = pA;
      ppart[ob*64 + mt*16 + gid + 8] = pB;
    }
    __syncthreads();
    if(tid<64) out[tok0+tid] = ppart[tid] + ppart[64+tid] + obv;
  }
}

// ---------------------------------------------------------------------------
extern "C" void kernel_launch(void* const* d_in, const int* in_sizes, int n_in,
                              void* d_out, int out_size) {
  const float* obs   =(const float*)d_in[0];
  const float* h0    =(const float*)d_in[1];
  const float* me_w1 =(const float*)d_in[2];
  const float* me_b1 =(const float*)d_in[3];
  const float* me_w2 =(const float*)d_in[4];
  const float* me_b2 =(const float*)d_in[5];
  const float* ae_w1 =(const float*)d_in[6];
  const float* ae_b1 =(const float*)d_in[7];
  const float* ae_w2 =(const float*)d_in[8];
  const float* ae_b2 =(const float*)d_in[9];
  const float* in_w  =(const float*)d_in[10];
  const float* in_b  =(const float*)d_in[11];
  const float* wo    =(const float*)d_in[12];
  const float* wob   =(const float*)d_in[13];
  const float* lng   =(const float*)d_in[14];
  const float* lnb   =(const float*)d_in[15];
  const float* w_ih  =(const float*)d_in[16];
  const float* w_hh  =(const float*)d_in[17];
  const float* b_ih  =(const float*)d_in[18];
  const float* b_hh  =(const float*)d_in[19];
  const float* mw0   =(const float*)d_in[20];
  const float* mb0   =(const float*)d_in[21];
  const float* mw1   =(const float*)d_in[22];
  const float* mb1   =(const float*)d_in[23];
  const float* out_w =(const float*)d_in[24];
  const float* out_b =(const float*)d_in[25];
  float* out=(float*)d_out;

  cudaFuncSetAttribute(k_front, cudaFuncAttributeMaxDynamicSharedMemorySize, SM1_BYTES);
  cudaFuncSetAttribute(k_xpP,   cudaFuncAttributeMaxDynamicSharedMemorySize, SM2_BYTES);
  cudaFuncSetAttribute(k_l0P,   cudaFuncAttributeMaxDynamicSharedMemorySize, SML0_BYTES);
  cudaFuncSetAttribute(k_l1P,   cudaFuncAttributeMaxDynamicSharedMemorySize, SML1_BYTES);

  float* xn;  cudaGetSymbolAddress((void**)&xn,  g_xn);
  float* xp;  cudaGetSymbolAddress((void**)&xp,  g_xp);
  float* gr;  cudaGetSymbolAddress((void**)&gr,  g_gru);

  k_front<<<1024,128,SM1_BYTES>>>(obs,me_w1,me_b1,me_w2,me_b2,
                                  ae_w1,ae_b1,ae_w2,ae_b2,
                                  in_w,in_b,wo,wob,lng,lnb,xn);
  k_xpP <<<dim3(74,2),256,SM2_BYTES>>>(xn,w_ih,b_ih,xp);
  k_gru <<<128,768>>>(xp,h0,w_hh,b_hh,gr,out);
  k_l0P <<<148,256,SML0_BYTES>>>(gr,mw0,mb0,xp);       // reuse g_xp as f0
  k_l1P <<<148,256,SML1_BYTES>>>(xp,mw1,mb1,out_w,out_b,out);
}

// round 15
// speedup vs baseline: 1.3113x; 1.3113x over previous
#include <cuda_runtime.h>
#include <math.h>

#define NTOK (128*1024)   // B=128, S=1024
typedef unsigned long long u64;
typedef unsigned int u32;

// ---------------- device scratch (static: no cudaMalloc allowed) ----------
__device__ __align__(128) float g_xn[(size_t)NTOK*64];
__device__ __align__(128) float g_xp[(size_t)NTOK*384];   // xp -> f0
__device__ __align__(128) float g_gru[(size_t)NTOK*128];

// ---------------- f32x2 helpers ---------------------------------------------
__device__ __forceinline__ u64 pk(float lo, float hi){
  u64 r; asm("mov.b64 %0,{%1,%2};" : "=l"(r) : "f"(lo), "f"(hi)); return r;
}
__device__ __forceinline__ void upk(u64 a, float& lo, float& hi){
  asm("mov.b64 {%0,%1},%2;" : "=f"(lo), "=f"(hi) : "l"(a));
}
__device__ __forceinline__ void fma2(u64& d, u64 a, u64 b){
  asm("fma.rn.f32x2 %0,%1,%2,%0;" : "+l"(d) : "l"(a), "l"(b));
}
__device__ __forceinline__ u64 add2(u64 a, u64 b){
  u64 r; asm("add.rn.f32x2 %0,%1,%2;" : "=l"(r) : "l"(a), "l"(b)); return r;
}
__device__ __forceinline__ float f2s(u64 a){
  float lo,hi; upk(a,lo,hi); return lo+hi;
}
__device__ __forceinline__ float lk(float x){ return fmaxf(x, 0.01f*x); }
__device__ __forceinline__ float sgm(float x){ return 1.0f/(1.0f+__expf(-x)); }
__device__ __forceinline__ float ftanh(float x){
  float e=__expf(2.0f*x); return 1.0f - 2.0f/(e+1.0f);
}

// ---------------- tf32 mma helpers ------------------------------------------
__device__ __forceinline__ u32 tf32c(float f){
  u32 r; asm("cvt.rna.tf32.f32 %0,%1;" : "=r"(r) : "f"(f)); return r;
}
__device__ __forceinline__ void tf32s(float f, u32& hi, u32& lo){
  hi = tf32c(f);
  lo = tf32c(f - __uint_as_float(hi));
}
__device__ __forceinline__ void mma8(float* d, const u32* a, const u32* b){
  asm("mma.sync.aligned.m16n8k8.row.col.f32.tf32.tf32.f32 "
      "{%0,%1,%2,%3},{%4,%5,%6,%7},{%8,%9},{%0,%1,%2,%3};"
      : "+f"(d[0]),"+f"(d[1]),"+f"(d[2]),"+f"(d[3])
      : "r"(a[0]),"r"(a[1]),"r"(a[2]),"r"(a[3]),"r"(b[0]),"r"(b[1]));
}

// packed dot products (k_front)
__device__ __forceinline__ float dot32p(const u64* __restrict__ w, const u64 (&x)[16]){
  u64 a0=0,a1=0,a2=0,a3=0;
  const ulonglong2* w2=(const ulonglong2*)w;
#pragma unroll
  for(int k=0;k<4;k++){
    ulonglong2 v0=w2[2*k], v1=w2[2*k+1];
    fma2(a0,v0.x,x[4*k]);   fma2(a1,v0.y,x[4*k+1]);
    fma2(a2,v1.x,x[4*k+2]); fma2(a3,v1.y,x[4*k+3]);
  }
  return f2s(add2(add2(a0,a1),add2(a2,a3)));
}
__device__ __forceinline__ float dot64p(const u64* __restrict__ w, const u64 (&x)[32]){
  u64 a0=0,a1=0,a2=0,a3=0;
  const ulonglong2* w2=(const ulonglong2*)w;
#pragma unroll
  for(int k=0;k<8;k++){
    ulonglong2 v0=w2[2*k], v1=w2[2*k+1];
    fma2(a0,v0.x,x[4*k]);   fma2(a1,v0.y,x[4*k+1]);
    fma2(a2,v1.x,x[4*k+2]); fma2(a3,v1.y,x[4*k+3]);
  }
  return f2s(add2(add2(a0,a1),add2(a2,a3)));
}

// -------- kernel 1 SMEM layout (R6/R9, known-good) ---------------------------
#define OF_MEW1 0
#define OF_MEB1 96
#define OF_MEW2 128
#define OF_MEB2 2176
#define OF_AEW1 2240
#define OF_AEB1 2432
#define OF_AEW2 2464
#define OF_AEB2 4512
#define OF_INW  4576
#define OF_INB  16864
#define OF_WO   17056
#define OF_WOB  21152
#define OF_LNG  21216
#define OF_LNB  21280
#define OF_WTOT 21344
#define OF_BUFA (OF_WTOT)
#define OF_BUFB (OF_WTOT+8192)
#define OF_BUFC (OF_WTOT+16384)
#define OF_BUFD (OF_WTOT+24576)
#define SM1_FLOATS (OF_WTOT+32768)
#define SM1_BYTES  (SM1_FLOATS*4)

__device__ __forceinline__ void enc_m(const float* __restrict__ sm,
                                      u64* __restrict__ buf, int tid,
                                      float x0, float x1, float x2){
  u64 hp[16];
#pragma unroll
  for(int j=0;j<32;j+=2){
    float a0 = sm[OF_MEB1+j]   + sm[OF_MEW1+j*3+0]*x0 + sm[OF_MEW1+j*3+1]*x1 + sm[OF_MEW1+j*3+2]*x2;
    float a1 = sm[OF_MEB1+j+1] + sm[OF_MEW1+j*3+3]*x0 + sm[OF_MEW1+j*3+4]*x1 + sm[OF_MEW1+j*3+5]*x2;
    hp[j>>1]=pk(lk(a0),lk(a1));
  }
#pragma unroll 1
  for(int o=0;o<64;o+=2){
    float y0 = sm[OF_MEB2+o]   + dot32p((const u64*)(sm+OF_MEW2+o*32),hp);
    float y1 = sm[OF_MEB2+o+1] + dot32p((const u64*)(sm+OF_MEW2+(o+1)*32),hp);
    buf[(o>>1)*128+tid]=pk(y0,y1);
  }
}

// ------------- kernel 1: encoders + attention + residual + LayerNorm -------
__global__ void __launch_bounds__(128) k_front(
  const float* __restrict__ obs,
  const float* __restrict__ me_w1, const float* __restrict__ me_b1,
  const float* __restrict__ me_w2, const float* __restrict__ me_b2,
  const float* __restrict__ ae_w1, const float* __restrict__ ae_b1,
  const float* __restrict__ ae_w2, const float* __restrict__ ae_b2,
  const float* __restrict__ in_w,  const float* __restrict__ in_b,
  const float* __restrict__ wo,    const float* __restrict__ wob,
  const float* __restrict__ lng,   const float* __restrict__ lnb,
  float* __restrict__ xn_out)
{
  extern __shared__ __align__(16) float sm[];
  const int tid=threadIdx.x;
  {
    const float* srcs[14]={me_w1,me_b1,me_w2,me_b2,ae_w1,ae_b1,ae_w2,ae_b2,in_w,in_b,wo,wob,lng,lnb};
    const int offs[14]={OF_MEW1,OF_MEB1,OF_MEW2,OF_MEB2,OF_AEW1,OF_AEB1,OF_AEW2,OF_AEB2,OF_INW,OF_INB,OF_WO,OF_WOB,OF_LNG,OF_LNB};
    const int lens[14]={96,32,2048,64,192,32,2048,64,12288,192,4096,64,64,64};
    for(int a=0;a<14;a++)
      for(int i=tid;i<lens[a];i+=128) sm[offs[a]+i]=srcs[a][i];
  }
  __syncthreads();
  u64* bA=(u64*)(sm+OF_BUFA);
  u64* bB=(u64*)(sm+OF_BUFB);
  u64* bC=(u64*)(sm+OF_BUFC);
  u64* bD=(u64*)(sm+OF_BUFD);

  const size_t tok=(size_t)blockIdx.x*128+tid;
  float ob[12];
  {
    const float4* p=(const float4*)(obs+tok*12);
    float4 v0=p[0],v1=p[1],v2=p[2];
    ob[0]=v0.x; ob[1]=v0.y; ob[2]=v0.z; ob[3]=v0.w;
    ob[4]=v1.x; ob[5]=v1.y; ob[6]=v1.z; ob[7]=v1.w;
    ob[8]=v2.x; ob[9]=v2.y; ob[10]=v2.z; ob[11]=v2.w;
  }

  // ---- ace -> bA
  {
    u64 hp[16];
#pragma unroll
    for(int j=0;j<32;j+=2){
      float a0=sm[OF_AEB1+j], a1=sm[OF_AEB1+j+1];
#pragma unroll
      for(int i=0;i<6;i++){ a0+=sm[OF_AEW1+j*6+i]*ob[6+i]; a1+=sm[OF_AEW1+(j+1)*6+i]*ob[6+i]; }
      hp[j>>1]=pk(lk(a0),lk(a1));
    }
#pragma unroll 1
    for(int o=0;o<64;o+=2){
      float y0=sm[OF_AEB2+o]  +dot32p((const u64*)(sm+OF_AEW2+o*32),hp);
      float y1=sm[OF_AEB2+o+1]+dot32p((const u64*)(sm+OF_AEW2+(o+1)*32),hp);
      bA[(o>>1)*128+tid]=pk(y0,y1);
    }
  }
  // ---- q = Wq@ace + bq -> bB
  {
    u64 ar[32];
#pragma unroll
    for(int k=0;k<32;k++) ar[k]=bA[k*128+tid];
#pragma unroll 1
    for(int o=0;o<64;o+=2){
      float y0=sm[OF_INB+o]  +dot64p((const u64*)(sm+OF_INW+(size_t)o*64),ar);
      float y1=sm[OF_INB+o+1]+dot64p((const u64*)(sm+OF_INW+(size_t)(o+1)*64),ar);
      bB[(o>>1)*128+tid]=pk(y0,y1);
    }
  }
  enc_m(sm,bC,tid,ob[0],ob[1],ob[2]);
  enc_m(sm,bD,tid,ob[3],ob[4],ob[5]);

  float a0h[4];
  {
    u64 er[32];
#pragma unroll
    for(int k=0;k<32;k++) er[k]=bC[k*128+tid];
    float s0[4];
#pragma unroll
    for(int h=0;h<4;h++){
      float acc=0.f;
#pragma unroll 1
      for(int oo=0;oo<16;oo+=2){ int o=h*16+oo;
        float q0,q1; upk(bB[(o>>1)*128+tid],q0,q1);
        float k0=sm[OF_INB+64+o]  +dot64p((const u64*)(sm+OF_INW+(size_t)(64+o)*64),er);
        float k1=sm[OF_INB+64+o+1]+dot64p((const u64*)(sm+OF_INW+(size_t)(65+o)*64),er);
        acc+=q0*k0+q1*k1;
      }
      s0[h]=acc;
    }
#pragma unroll
    for(int k=0;k<32;k++) er[k]=bD[k*128+tid];
#pragma unroll
    for(int h=0;h<4;h++){
      float acc=0.f;
#pragma unroll 1
      for(int oo=0;oo<16;oo+=2){ int o=h*16+oo;
        float q0,q1; upk(bB[(o>>1)*128+tid],q0,q1);
        float k0=sm[OF_INB+64+o]  +dot64p((const u64*)(sm+OF_INW+(size_t)(64+o)*64),er);
        float k1=sm[OF_INB+64+o+1]+dot64p((const u64*)(sm+OF_INW+(size_t)(65+o)*64),er);
        acc+=q0*k0+q1*k1;
      }
      a0h[h]=sgm((s0[h]-acc)*0.25f);
    }
  }
  {
    u64 m1r[32], m2r[32];
#pragma unroll
    for(int k=0;k<32;k++){ m1r[k]=bC[k*128+tid]; m2r[k]=bD[k*128+tid]; }
#pragma unroll
    for(int h=0;h<4;h++){
      float a0=a0h[h], a1=1.0f-a0h[h];
#pragma unroll 1
      for(int oo=0;oo<16;oo+=2){ int o=h*16+oo;
        const u64* r0=(const u64*)(sm+OF_INW+(size_t)(128+o)*64);
        const u64* r1=(const u64*)(sm+OF_INW+(size_t)(129+o)*64);
        float y0=sm[OF_INB+128+o]  +a0*dot64p(r0,m1r)+a1*dot64p(r0,m2r);
        float y1=sm[OF_INB+128+o+1]+a0*dot64p(r1,m1r)+a1*dot64p(r1,m2r);
        bB[(o>>1)*128+tid]=pk(y0,y1);
      }
    }
  }
  float mu,rs;
  {
    u64 cr[32];
#pragma unroll
    for(int k=0;k<32;k++) cr[k]=bB[k*128+tid];
    float sum=0.f,sq=0.f;
#pragma unroll 1
    for(int o=0;o<64;o+=2){
      float a0v,a1v; upk(bA[(o>>1)*128+tid],a0v,a1v);
      float x0=sm[OF_WOB+o]  +dot64p((const u64*)(sm+OF_WO+(size_t)o*64),cr)+a0v;
      float x1=sm[OF_WOB+o+1]+dot64p((const u64*)(sm+OF_WO+(size_t)(o+1)*64),cr)+a1v;
      bC[(o>>1)*128+tid]=pk(x0,x1);
      sum+=x0+x1; sq+=x0*x0+x1*x1;
    }
    mu=sum*(1.0f/64.0f);
    float var=sq*(1.0f/64.0f)-mu*mu;
    rs=rsqrtf(var+1e-5f);
  }
  float* op = xn_out + tok*64;
#pragma unroll 1
  for(int o=0;o<64;o+=4){
    float x0,x1,x2,x3;
    upk(bC[(o>>1)*128+tid],x0,x1);
    upk(bC[((o>>1)+1)*128+tid],x2,x3);
    float4 v;
    v.x=(x0-mu)*rs*sm[OF_LNG+o+0]+sm[OF_LNB+o+0];
    v.y=(x1-mu)*rs*sm[OF_LNG+o+1]+sm[OF_LNB+o+1];
    v.z=(x2-mu)*rs*sm[OF_LNG+o+2]+sm[OF_LNB+o+2];
    v.w=(x3-mu)*rs*sm[OF_LNG+o+3]+sm[OF_LNB+o+3];
    *(float4*)(op+o)=v;
  }
}

// ============== kernel 2: xp GEMM (persistent split-tf32, 512 thr) ==========
#define XPAD 68
#define SM2_WORDS (43520+192)
#define SM2_BYTES (SM2_WORDS*4)
__global__ void __launch_bounds__(512,1) k_xpP(
  const float* __restrict__ xn, const float* __restrict__ w_ih,
  const float* __restrict__ b_ih, float* __restrict__ xp)
{
  extern __shared__ __align__(16) u32 smw[];
  u32* Whi = smw;
  u32* Wlo = smw + 13056;
  u32* Xhi = smw + 26112;
  u32* Xlo = smw + 34816;
  float* bs = (float*)(smw + 43520);
  const int tid = threadIdx.x;
  const int oh = blockIdx.y;
  for(int i=tid;i<12288;i+=512){
    int n=i>>6, k=i&63;
    u32 hi,lo; tf32s(w_ih[(size_t)(oh*192+n)*64+k],hi,lo);
    Whi[n*XPAD+k]=hi; Wlo[n*XPAD+k]=lo;
  }
  for(int i=tid;i<192;i+=512) bs[i]=b_ih[oh*192+i];

  const int lane=tid&31, gid=lane>>2, tig=lane&3;
  const int w=tid>>5, tokblk=w>>2, ob=w&3;   // 4 tok-blocks x 32, 4 out-blocks x 48

#pragma unroll 1
  for(int t=blockIdx.x; t<1024; t+=74){
    const size_t tok0=(size_t)t*128;
    __syncthreads();
    for(int i=tid;i<8192;i+=512){
      int tt=i>>6, k=i&63;
      u32 hi,lo; tf32s(xn[tok0*64+i],hi,lo);
      Xhi[tt*XPAD+k]=hi; Xlo[tt*XPAD+k]=lo;
    }
    __syncthreads();

    float d[2][6][4];
#pragma unroll
    for(int m=0;m<2;m++)
#pragma unroll
      for(int n=0;n<6;n++)
#pragma unroll
        for(int r=0;r<4;r++) d[m][n][r]=0.f;

#pragma unroll
    for(int ks=0;ks<8;ks++){
      u32 ah0[4],al0[4],ah1[4],al1[4];
      {
        const u32* p;
        p = Xhi + (tokblk*32+gid)*XPAD + ks*8 + tig;
        ah0[0]=p[0]; ah0[1]=p[8*XPAD]; ah0[2]=p[4]; ah0[3]=p[8*XPAD+4];
        p = Xlo + (tokblk*32+gid)*XPAD + ks*8 + tig;
        al0[0]=p[0]; al0[1]=p[8*XPAD]; al0[2]=p[4]; al0[3]=p[8*XPAD+4];
        p = Xhi + (tokblk*32+16+gid)*XPAD + ks*8 + tig;
        ah1[0]=p[0]; ah1[1]=p[8*XPAD]; ah1[2]=p[4]; ah1[3]=p[8*XPAD+4];
        p = Xlo + (tokblk*32+16+gid)*XPAD + ks*8 + tig;
        al1[0]=p[0]; al1[1]=p[8*XPAD]; al1[2]=p[4]; al1[3]=p[8*XPAD+4];
      }
#pragma unroll
      for(int n=0;n<6;n++){
        const u32* bh = Whi + (ob*48+n*8+gid)*XPAD + ks*8 + tig;
        u32 bhf[2]={bh[0],bh[4]};
        const u32* bl = Wlo + (ob*48+n*8+gid)*XPAD + ks*8 + tig;
        u32 blf[2]={bl[0],bl[4]};
        mma8(d[0][n],ah0,bhf); mma8(d[0][n],al0,bhf); mma8(d[0][n],ah0,blf);
        mma8(d[1][n],ah1,bhf); mma8(d[1][n],al1,bhf); mma8(d[1][n],ah1,blf);
      }
    }
#pragma unroll
    for(int m=0;m<2;m++){
      int row = tokblk*32+m*16+gid;
#pragma unroll
      for(int n=0;n<6;n++){
        int lc = ob*48+n*8+tig*2;
        int gc = oh*192+lc;
        float2 v0 = make_float2(d[m][n][0]+bs[lc], d[m][n][1]+bs[lc+1]);
        float2 v1 = make_float2(d[m][n][2]+bs[lc], d[m][n][3]+bs[lc+1]);
        *(float2*)(xp + (tok0+row)*384 + gc)   = v0;
        *(float2*)(xp + (tok0+row+8)*384 + gc) = v1;
      }
    }
  }
}

// ============== kernel 3: GRU scan (R12-proven, fast tanh) ==================
__global__ void __launch_bounds__(384,1) k_gru(
  const float* __restrict__ xp, const float* __restrict__ h0,
  const float* __restrict__ w_hh, const float* __restrict__ b_hh,
  float* __restrict__ gru_out, float* __restrict__ out)
{
  __shared__ __align__(16) float hs[128];
  __shared__ float sr[128], sz[128], sxg[128], shg[128];
  const int j=threadIdx.x, b=blockIdx.x;
  u64 w2[64];
  {
    const ulonglong2* wr=(const ulonglong2*)(w_hh+(size_t)j*128);
#pragma unroll
    for(int k=0;k<32;k++){ ulonglong2 v=wr[k]; w2[2*k]=v.x; w2[2*k+1]=v.y; }
  }
  const float bj=b_hh[j];
  if(j<128) hs[j]=h0[b*128+j];
  __syncthreads();
  const float* xbase = xp + (size_t)b*1024*384 + j;
  float* gbase = gru_out + (size_t)b*1024*128;
  const int i = j & 127;
  float xt = xbase[0];
#pragma unroll 1
  for(int t=0;t<1024;t++){
    float xt_n = (t<1023) ? xbase[(size_t)(t+1)*384] : 0.f;
    const ulonglong2* h2=(const ulonglong2*)hs;
    u64 a0=0,a1=0,a2=0,a3=0;
#pragma unroll
    for(int k=0;k<32;k+=2){
      ulonglong2 v0=h2[k], v1=h2[k+1];
      fma2(a0,w2[2*k],v0.x);   fma2(a1,w2[2*k+1],v0.y);
      fma2(a2,w2[2*k+2],v1.x); fma2(a3,w2[2*k+3],v1.y);
    }
    float acc=f2s(add2(add2(a0,a1),add2(a2,a3)));
    if(j<128)       sr[i]=xt+bj+acc;
    else if(j<256)  sz[i]=xt+bj+acc;
    else          { shg[i]=bj+acc; sxg[i]=xt; }
    __syncthreads();
    if(j<128){
      float r=sgm(sr[i]);
      float z=sgm(sz[i]);
      float g=ftanh(sxg[i]+r*shg[i]);
      float hn=z*(hs[i]-g)+g;           // (1-z)*g + z*h
      gbase[(size_t)t*128+i]=hn;
      hs[i]=hn;
    }
    __syncthreads();
    xt = xt_n;
  }
  if(j<128) out[(size_t)NTOK + (size_t)b*128 + j] = hs[j];
}

// ============== kernel 4a: MLP layer 0 (persistent, 512 thr) ================
#define MPAD 132
#define SML0_WORDS (50688+128)
#define SML0_BYTES (SML0_WORDS*4)
__global__ void __launch_bounds__(512,1) k_l0P(
  const float* __restrict__ gin,
  const float* __restrict__ w0, const float* __restrict__ b0,
  float* __restrict__ f0)
{
  extern __shared__ __align__(16) u32 smw[];
  u32* Whi = smw;
  u32* Wlo = smw + 16896;
  u32* Xhi = smw + 33792;
  u32* Xlo = smw + 42240;
  float* b0s = (float*)(smw + 50688);
  const int tid = threadIdx.x;
  for(int i=tid;i<16384;i+=512){
    int n=i>>7, k=i&127;
    u32 hi,lo; tf32s(w0[i],hi,lo);
    Whi[n*MPAD+k]=hi; Wlo[n*MPAD+k]=lo;
  }
  if(tid<128) b0s[tid]=b0[tid];

  const int lane=tid&31, gid=lane>>2, tig=lane&3;
  const int w=tid>>5, mt=w&3, ob=w>>2;   // 4 m-tiles x 16 tok, 4 out-blocks x 32

#pragma unroll 1
  for(int t=blockIdx.x; t<2048; t+=148){
    const size_t tok0=(size_t)t*64;
    __syncthreads();
    for(int i=tid;i<8192;i+=512){
      int tt=i>>7, k=i&127;
      u32 hi,lo; tf32s(gin[tok0*128+i],hi,lo);
      Xhi[tt*MPAD+k]=hi; Xlo[tt*MPAD+k]=lo;
    }
    __syncthreads();

    float d[4][4];
#pragma unroll
    for(int n=0;n<4;n++){ d[n][0]=0;d[n][1]=0;d[n][2]=0;d[n][3]=0; }
#pragma unroll
    for(int ks=0;ks<16;ks++){
      const u32* ph = Xhi + (mt*16+gid)*MPAD + ks*8 + tig;
      u32 ah[4]={ph[0], ph[8*MPAD], ph[4], ph[8*MPAD+4]};
      const u32* pl = Xlo + (mt*16+gid)*MPAD + ks*8 + tig;
      u32 al[4]={pl[0], pl[8*MPAD], pl[4], pl[8*MPAD+4]};
#pragma unroll
      for(int n=0;n<4;n++){
        const u32* bh = Whi + (ob*32+n*8+gid)*MPAD + ks*8 + tig;
        u32 bhf[2]={bh[0],bh[4]};
        const u32* bl = Wlo + (ob*32+n*8+gid)*MPAD + ks*8 + tig;
        u32 blf[2]={bl[0],bl[4]};
        mma8(d[n],ah,bhf); mma8(d[n],al,bhf); mma8(d[n],ah,blf);
      }
    }
    int row = mt*16+gid;
#pragma unroll
    for(int n=0;n<4;n++){
      int col = ob*32+n*8+tig*2;
      float2 v0 = make_float2(lk(d[n][0]+b0s[col]), lk(d[n][1]+b0s[col+1]));
      float2 v1 = make_float2(lk(d[n][2]+b0s[col]), lk(d[n][3]+b0s[col+1]));
      *(float2*)(f0 + (tok0+row)*128 + col)   = v0;
      *(float2*)(f0 + (tok0+row+8)*128 + col) = v1;
    }
  }
}

// ============== kernel 4b: MLP layer 1 + value head (persistent, 512 thr) ===
#define SML1_WORDS (50944+256)
#define SML1_BYTES (SML1_WORDS*4)
__global__ void __launch_bounds__(512,1) k_l1P(
  const float* __restrict__ f0in,
  const float* __restrict__ w1, const float* __restrict__ b1,
  const float* __restrict__ ow, const float* __restrict__ obias,
  float* __restrict__ out)
{
  extern __shared__ __align__(16) u32 smw[];
  u32* Whi = smw;
  u32* Wlo = smw + 16896;
  u32* Xhi = smw + 33792;
  u32* Xlo = smw + 42240;
  float* b1s = (float*)(smw + 50688);
  float* ows = (float*)(smw + 50816);
  float* ppart = (float*)(smw + 50944);   // 256 floats: 4 obs x 64 tokens
  const int tid = threadIdx.x;
  for(int i=tid;i<16384;i+=512){
    int n=i>>7, k=i&127;
    u32 hi,lo; tf32s(w1[i],hi,lo);
    Whi[n*MPAD+k]=hi; Wlo[n*MPAD+k]=lo;
  }
  if(tid<128){ b1s[tid]=b1[tid]; ows[tid]=ow[tid]; }
  const float obv = obias[0];

  const int lane=tid&31, gid=lane>>2, tig=lane&3;
  const int w=tid>>5, mt=w&3, ob=w>>2;

#pragma unroll 1
  for(int t=blockIdx.x; t<2048; t+=148){
    const size_t tok0=(size_t)t*64;
    __syncthreads();
    for(int i=tid;i<8192;i+=512){
      int tt=i>>7, k=i&127;
      u32 hi,lo; tf32s(f0in[tok0*128+i],hi,lo);
      Xhi[tt*MPAD+k]=hi; Xlo[tt*MPAD+k]=lo;
    }
    __syncthreads();

    float d[4][4];
#pragma unroll
    for(int n=0;n<4;n++){ d[n][0]=0;d[n][1]=0;d[n][2]=0;d[n][3]=0; }
#pragma unroll
    for(int ks=0;ks<16;ks++){
      const u32* ph = Xhi + (mt*16+gid)*MPAD + ks*8 + tig;
      u32 ah[4]={ph[0], ph[8*MPAD], ph[4], ph[8*MPAD+4]};
      const u32* pl = Xlo + (mt*16+gid)*MPAD + ks*8 + tig;
      u32 al[4]={pl[0], pl[8*MPAD], pl[4], pl[8*MPAD+4]};
#pragma unroll
      for(int n=0;n<4;n++){
        const u32* bh = Whi + (ob*32+n*8+gid)*MPAD + ks*8 + tig;
        u32 bhf[2]={bh[0],bh[4]};
        const u32* bl = Wlo + (ob*32+n*8+gid)*MPAD + ks*8 + tig;
        u32 blf[2]={bl[0],bl[4]};
        mma8(d[n],ah,bhf); mma8(d[n],al,bhf); mma8(d[n],ah,blf);
      }
    }
    float pA=0.f, pB=0.f;
#pragma unroll
    for(int n=0;n<4;n++){
      int col = ob*32+n*8+tig*2;
      pA += ows[col]*lk(d[n][0]+b1s[col]) + ows[col+1]*lk(d[n][1]+b1s[col+1]);
      pB += ows[col]*lk(d[n][2]+b1s[col]) + ows[col+1]*lk(d[n][3]+b1s[col+1]);
    }
    pA += __shfl_xor_sync(0xFFFFFFFF,pA,1); pA += __shfl_xor_sync(0xFFFFFFFF,pA,2);
    pB += __shfl_xor_sync(0xFFFFFFFF,pB,1); pB += __shfl_xor_sync(0xFFFFFFFF,pB,2);
    if(tig==0){
      ppart[ob*64 + mt*16 + gid]     = pA;
      ppart[ob*64 + mt*16 + gid + 8] = pB;
    }
    __syncthreads();
    if(tid<64)
      out[tok0+tid] = ppart[tid] + ppart[64+tid] + ppart[128+tid] + ppart[192+tid] + obv;
  }
}

// ---------------------------------------------------------------------------
extern "C" void kernel_launch(void* const* d_in, const int* in_sizes, int n_in,
                              void* d_out, int out_size) {
  const float* obs   =(const float*)d_in[0];
  const float* h0    =(const float*)d_in[1];
  const float* me_w1 =(const float*)d_in[2];
  const float* me_b1 =(const float*)d_in[3];
  const float* me_w2 =(const float*)d_in[4];
  const float* me_b2 =(const float*)d_in[5];
  const float* ae_w1 =(const float*)d_in[6];
  const float* ae_b1 =(const float*)d_in[7];
  const float* ae_w2 =(const float*)d_in[8];
  const float* ae_b2 =(const float*)d_in[9];
  const float* in_w  =(const float*)d_in[10];
  const float* in_b  =(const float*)d_in[11];
  const float* wo    =(const float*)d_in[12];
  const float* wob   =(const float*)d_in[13];
  const float* lng   =(const float*)d_in[14];
  const float* lnb   =(const float*)d_in[15];
  const float* w_ih  =(const float*)d_in[16];
  const float* w_hh  =(const float*)d_in[17];
  const float* b_ih  =(const float*)d_in[18];
  const float* b_hh  =(const float*)d_in[19];
  const float* mw0   =(const float*)d_in[20];
  const float* mb0   =(const float*)d_in[21];
  const float* mw1   =(const float*)d_in[22];
  const float* mb1   =(const float*)d_in[23];
  const float* out_w =(const float*)d_in[24];
  const float* out_b =(const float*)d_in[25];
  float* out=(float*)d_out;

  cudaFuncSetAttribute(k_front, cudaFuncAttributeMaxDynamicSharedMemorySize, SM1_BYTES);
  cudaFuncSetAttribute(k_xpP,   cudaFuncAttributeMaxDynamicSharedMemorySize, SM2_BYTES);
  cudaFuncSetAttribute(k_l0P,   cudaFuncAttributeMaxDynamicSharedMemorySize, SML0_BYTES);
  cudaFuncSetAttribute(k_l1P,   cudaFuncAttributeMaxDynamicSharedMemorySize, SML1_BYTES);

  float* xn;  cudaGetSymbolAddress((void**)&xn,  g_xn);
  float* xp;  cudaGetSymbolAddress((void**)&xp,  g_xp);
  float* gr;  cudaGetSymbolAddress((void**)&gr,  g_gru);

  k_front<<<1024,128,SM1_BYTES>>>(obs,me_w1,me_b1,me_w2,me_b2,
                                  ae_w1,ae_b1,ae_w2,ae_b2,
                                  in_w,in_b,wo,wob,lng,lnb,xn);
  k_xpP <<<dim3(74,2),512,SM2_BYTES>>>(xn,w_ih,b_ih,xp);
  k_gru <<<128,384>>>(xp,h0,w_hh,b_hh,gr,out);
  k_l0P <<<148,512,SML0_BYTES>>>(gr,mw0,mb0,xp);       // reuse g_xp as f0
  k_l1P <<<148,512,SML1_BYTES>>>(xp,mw1,mb1,out_w,out_b,out);
}

// round 16
// speedup vs baseline: 1.3268x; 1.0118x over previous
#include <cuda_runtime.h>
#include <math.h>

#define NTOK (128*1024)   // B=128, S=1024
typedef unsigned long long u64;
typedef unsigned int u32;

// ---------------- device scratch (static: no cudaMalloc allowed) ----------
__device__ __align__(128) float g_xn[(size_t)NTOK*64];
__device__ __align__(128) float g_xp[(size_t)NTOK*384];   // xp -> f0
__device__ __align__(128) float g_gru[(size_t)NTOK*128];

// ---------------- f32x2 helpers ---------------------------------------------
__device__ __forceinline__ u64 pk(float lo, float hi){
  u64 r; asm("mov.b64 %0,{%1,%2};" : "=l"(r) : "f"(lo), "f"(hi)); return r;
}
__device__ __forceinline__ void upk(u64 a, float& lo, float& hi){
  asm("mov.b64 {%0,%1},%2;" : "=f"(lo), "=f"(hi) : "l"(a));
}
__device__ __forceinline__ void fma2(u64& d, u64 a, u64 b){
  asm("fma.rn.f32x2 %0,%1,%2,%0;" : "+l"(d) : "l"(a), "l"(b));
}
__device__ __forceinline__ u64 add2(u64 a, u64 b){
  u64 r; asm("add.rn.f32x2 %0,%1,%2;" : "=l"(r) : "l"(a), "l"(b)); return r;
}
__device__ __forceinline__ float f2s(u64 a){
  float lo,hi; upk(a,lo,hi); return lo+hi;
}
__device__ __forceinline__ float lk(float x){ return fmaxf(x, 0.01f*x); }
__device__ __forceinline__ float sgm(float x){ return 1.0f/(1.0f+__expf(-x)); }
__device__ __forceinline__ float ftanh(float x){
  float e=__expf(2.0f*x); return 1.0f - 2.0f/(e+1.0f);
}

// ---------------- tf32 mma helpers ------------------------------------------
__device__ __forceinline__ u32 tf32c(float f){
  u32 r; asm("cvt.rna.tf32.f32 %0,%1;" : "=r"(r) : "f"(f)); return r;
}
__device__ __forceinline__ void tf32s(float f, u32& hi, u32& lo){
  hi = tf32c(f);
  lo = tf32c(f - __uint_as_float(hi));
}
__device__ __forceinline__ void mma8(float* d, const u32* a, const u32* b){
  asm("mma.sync.aligned.m16n8k8.row.col.f32.tf32.tf32.f32 "
      "{%0,%1,%2,%3},{%4,%5,%6,%7},{%8,%9},{%0,%1,%2,%3};"
      : "+f"(d[0]),"+f"(d[1]),"+f"(d[2]),"+f"(d[3])
      : "r"(a[0]),"r"(a[1]),"r"(a[2]),"r"(a[3]),"r"(b[0]),"r"(b[1]));
}

// packed dot products (k_front)
__device__ __forceinline__ float dot32p(const u64* __restrict__ w, const u64 (&x)[16]){
  u64 a0=0,a1=0,a2=0,a3=0;
  const ulonglong2* w2=(const ulonglong2*)w;
#pragma unroll
  for(int k=0;k<4;k++){
    ulonglong2 v0=w2[2*k], v1=w2[2*k+1];
    fma2(a0,v0.x,x[4*k]);   fma2(a1,v0.y,x[4*k+1]);
    fma2(a2,v1.x,x[4*k+2]); fma2(a3,v1.y,x[4*k+3]);
  }
  return f2s(add2(add2(a0,a1),add2(a2,a3)));
}
__device__ __forceinline__ float dot64p(const u64* __restrict__ w, const u64 (&x)[32]){
  u64 a0=0,a1=0,a2=0,a3=0;
  const ulonglong2* w2=(const ulonglong2*)w;
#pragma unroll
  for(int k=0;k<8;k++){
    ulonglong2 v0=w2[2*k], v1=w2[2*k+1];
    fma2(a0,v0.x,x[4*k]);   fma2(a1,v0.y,x[4*k+1]);
    fma2(a2,v1.x,x[4*k+2]); fma2(a3,v1.y,x[4*k+3]);
  }
  return f2s(add2(add2(a0,a1),add2(a2,a3)));
}

// -------- kernel 1 SMEM layout (R6/R9, known-good) ---------------------------
#define OF_MEW1 0
#define OF_MEB1 96
#define OF_MEW2 128
#define OF_MEB2 2176
#define OF_AEW1 2240
#define OF_AEB1 2432
#define OF_AEW2 2464
#define OF_AEB2 4512
#define OF_INW  4576
#define OF_INB  16864
#define OF_WO   17056
#define OF_WOB  21152
#define OF_LNG  21216
#define OF_LNB  21280
#define OF_WTOT 21344
#define OF_BUFA (OF_WTOT)
#define OF_BUFB (OF_WTOT+8192)
#define OF_BUFC (OF_WTOT+16384)
#define OF_BUFD (OF_WTOT+24576)
#define SM1_FLOATS (OF_WTOT+32768)
#define SM1_BYTES  (SM1_FLOATS*4)

__device__ __forceinline__ void enc_m(const float* __restrict__ sm,
                                      u64* __restrict__ buf, int tid,
                                      float x0, float x1, float x2){
  u64 hp[16];
#pragma unroll
  for(int j=0;j<32;j+=2){
    float a0 = sm[OF_MEB1+j]   + sm[OF_MEW1+j*3+0]*x0 + sm[OF_MEW1+j*3+1]*x1 + sm[OF_MEW1+j*3+2]*x2;
    float a1 = sm[OF_MEB1+j+1] + sm[OF_MEW1+j*3+3]*x0 + sm[OF_MEW1+j*3+4]*x1 + sm[OF_MEW1+j*3+5]*x2;
    hp[j>>1]=pk(lk(a0),lk(a1));
  }
#pragma unroll 1
  for(int o=0;o<64;o+=2){
    float y0 = sm[OF_MEB2+o]   + dot32p((const u64*)(sm+OF_MEW2+o*32),hp);
    float y1 = sm[OF_MEB2+o+1] + dot32p((const u64*)(sm+OF_MEW2+(o+1)*32),hp);
    buf[(o>>1)*128+tid]=pk(y0,y1);
  }
}

// ------------- kernel 1: encoders + attention + residual + LayerNorm -------
__global__ void __launch_bounds__(128) k_front(
  const float* __restrict__ obs,
  const float* __restrict__ me_w1, const float* __restrict__ me_b1,
  const float* __restrict__ me_w2, const float* __restrict__ me_b2,
  const float* __restrict__ ae_w1, const float* __restrict__ ae_b1,
  const float* __restrict__ ae_w2, const float* __restrict__ ae_b2,
  const float* __restrict__ in_w,  const float* __restrict__ in_b,
  const float* __restrict__ wo,    const float* __restrict__ wob,
  const float* __restrict__ lng,   const float* __restrict__ lnb,
  float* __restrict__ xn_out)
{
  extern __shared__ __align__(16) float sm[];
  const int tid=threadIdx.x;
  {
    const float* srcs[14]={me_w1,me_b1,me_w2,me_b2,ae_w1,ae_b1,ae_w2,ae_b2,in_w,in_b,wo,wob,lng,lnb};
    const int offs[14]={OF_MEW1,OF_MEB1,OF_MEW2,OF_MEB2,OF_AEW1,OF_AEB1,OF_AEW2,OF_AEB2,OF_INW,OF_INB,OF_WO,OF_WOB,OF_LNG,OF_LNB};
    const int lens[14]={96,32,2048,64,192,32,2048,64,12288,192,4096,64,64,64};
    for(int a=0;a<14;a++)
      for(int i=tid;i<lens[a];i+=128) sm[offs[a]+i]=srcs[a][i];
  }
  __syncthreads();
  u64* bA=(u64*)(sm+OF_BUFA);
  u64* bB=(u64*)(sm+OF_BUFB);
  u64* bC=(u64*)(sm+OF_BUFC);
  u64* bD=(u64*)(sm+OF_BUFD);

  const size_t tok=(size_t)blockIdx.x*128+tid;
  float ob[12];
  {
    const float4* p=(const float4*)(obs+tok*12);
    float4 v0=p[0],v1=p[1],v2=p[2];
    ob[0]=v0.x; ob[1]=v0.y; ob[2]=v0.z; ob[3]=v0.w;
    ob[4]=v1.x; ob[5]=v1.y; ob[6]=v1.z; ob[7]=v1.w;
    ob[8]=v2.x; ob[9]=v2.y; ob[10]=v2.z; ob[11]=v2.w;
  }

  // ---- ace -> bA
  {
    u64 hp[16];
#pragma unroll
    for(int j=0;j<32;j+=2){
      float a0=sm[OF_AEB1+j], a1=sm[OF_AEB1+j+1];
#pragma unroll
      for(int i=0;i<6;i++){ a0+=sm[OF_AEW1+j*6+i]*ob[6+i]; a1+=sm[OF_AEW1+(j+1)*6+i]*ob[6+i]; }
      hp[j>>1]=pk(lk(a0),lk(a1));
    }
#pragma unroll 1
    for(int o=0;o<64;o+=2){
      float y0=sm[OF_AEB2+o]  +dot32p((const u64*)(sm+OF_AEW2+o*32),hp);
      float y1=sm[OF_AEB2+o+1]+dot32p((const u64*)(sm+OF_AEW2+(o+1)*32),hp);
      bA[(o>>1)*128+tid]=pk(y0,y1);
    }
  }
  // ---- q = Wq@ace + bq -> bB
  {
    u64 ar[32];
#pragma unroll
    for(int k=0;k<32;k++) ar[k]=bA[k*128+tid];
#pragma unroll 1
    for(int o=0;o<64;o+=2){
      float y0=sm[OF_INB+o]  +dot64p((const u64*)(sm+OF_INW+(size_t)o*64),ar);
      float y1=sm[OF_INB+o+1]+dot64p((const u64*)(sm+OF_INW+(size_t)(o+1)*64),ar);
      bB[(o>>1)*128+tid]=pk(y0,y1);
    }
  }
  enc_m(sm,bC,tid,ob[0],ob[1],ob[2]);
  enc_m(sm,bD,tid,ob[3],ob[4],ob[5]);

  float a0h[4];
  {
    u64 er[32];
#pragma unroll
    for(int k=0;k<32;k++) er[k]=bC[k*128+tid];
    float s0[4];
#pragma unroll
    for(int h=0;h<4;h++){
      float acc=0.f;
#pragma unroll 1
      for(int oo=0;oo<16;oo+=2){ int o=h*16+oo;
        float q0,q1; upk(bB[(o>>1)*128+tid],q0,q1);
        float k0=sm[OF_INB+64+o]  +dot64p((const u64*)(sm+OF_INW+(size_t)(64+o)*64),er);
        float k1=sm[OF_INB+64+o+1]+dot64p((const u64*)(sm+OF_INW+(size_t)(65+o)*64),er);
        acc+=q0*k0+q1*k1;
      }
      s0[h]=acc;
    }
#pragma unroll
    for(int k=0;k<32;k++) er[k]=bD[k*128+tid];
#pragma unroll
    for(int h=0;h<4;h++){
      float acc=0.f;
#pragma unroll 1
      for(int oo=0;oo<16;oo+=2){ int o=h*16+oo;
        float q0,q1; upk(bB[(o>>1)*128+tid],q0,q1);
        float k0=sm[OF_INB+64+o]  +dot64p((const u64*)(sm+OF_INW+(size_t)(64+o)*64),er);
        float k1=sm[OF_INB+64+o+1]+dot64p((const u64*)(sm+OF_INW+(size_t)(65+o)*64),er);
        acc+=q0*k0+q1*k1;
      }
      a0h[h]=sgm((s0[h]-acc)*0.25f);
    }
  }
  {
    u64 m1r[32], m2r[32];
#pragma unroll
    for(int k=0;k<32;k++){ m1r[k]=bC[k*128+tid]; m2r[k]=bD[k*128+tid]; }
#pragma unroll
    for(int h=0;h<4;h++){
      float a0=a0h[h], a1=1.0f-a0h[h];
#pragma unroll 1
      for(int oo=0;oo<16;oo+=2){ int o=h*16+oo;
        const u64* r0=(const u64*)(sm+OF_INW+(size_t)(128+o)*64);
        const u64* r1=(const u64*)(sm+OF_INW+(size_t)(129+o)*64);
        float y0=sm[OF_INB+128+o]  +a0*dot64p(r0,m1r)+a1*dot64p(r0,m2r);
        float y1=sm[OF_INB+128+o+1]+a0*dot64p(r1,m1r)+a1*dot64p(r1,m2r);
        bB[(o>>1)*128+tid]=pk(y0,y1);
      }
    }
  }
  float mu,rs;
  {
    u64 cr[32];
#pragma unroll
    for(int k=0;k<32;k++) cr[k]=bB[k*128+tid];
    float sum=0.f,sq=0.f;
#pragma unroll 1
    for(int o=0;o<64;o+=2){
      float a0v,a1v; upk(bA[(o>>1)*128+tid],a0v,a1v);
      float x0=sm[OF_WOB+o]  +dot64p((const u64*)(sm+OF_WO+(size_t)o*64),cr)+a0v;
      float x1=sm[OF_WOB+o+1]+dot64p((const u64*)(sm+OF_WO+(size_t)(o+1)*64),cr)+a1v;
      bC[(o>>1)*128+tid]=pk(x0,x1);
      sum+=x0+x1; sq+=x0*x0+x1*x1;
    }
    mu=sum*(1.0f/64.0f);
    float var=sq*(1.0f/64.0f)-mu*mu;
    rs=rsqrtf(var+1e-5f);
  }
  float* op = xn_out + tok*64;
#pragma unroll 1
  for(int o=0;o<64;o+=4){
    float x0,x1,x2,x3;
    upk(bC[(o>>1)*128+tid],x0,x1);
    upk(bC[((o>>1)+1)*128+tid],x2,x3);
    float4 v;
    v.x=(x0-mu)*rs*sm[OF_LNG+o+0]+sm[OF_LNB+o+0];
    v.y=(x1-mu)*rs*sm[OF_LNG+o+1]+sm[OF_LNB+o+1];
    v.z=(x2-mu)*rs*sm[OF_LNG+o+2]+sm[OF_LNB+o+2];
    v.w=(x3-mu)*rs*sm[OF_LNG+o+3]+sm[OF_LNB+o+3];
    *(float4*)(op+o)=v;
  }
}

// ============== kernel 2: xp GEMM (persistent split-tf32, 512 thr) ==========
#define XPAD 68
#define SM2_WORDS (43520+192)
#define SM2_BYTES (SM2_WORDS*4)
__global__ void __launch_bounds__(512,1) k_xpP(
  const float* __restrict__ xn, const float* __restrict__ w_ih,
  const float* __restrict__ b_ih, float* __restrict__ xp)
{
  extern __shared__ __align__(16) u32 smw[];
  u32* Whi = smw;
  u32* Wlo = smw + 13056;
  u32* Xhi = smw + 26112;
  u32* Xlo = smw + 34816;
  float* bs = (float*)(smw + 43520);
  const int tid = threadIdx.x;
  const int oh = blockIdx.y;
  for(int i=tid;i<12288;i+=512){
    int n=i>>6, k=i&63;
    u32 hi,lo; tf32s(w_ih[(size_t)(oh*192+n)*64+k],hi,lo);
    Whi[n*XPAD+k]=hi; Wlo[n*XPAD+k]=lo;
  }
  for(int i=tid;i<192;i+=512) bs[i]=b_ih[oh*192+i];

  const int lane=tid&31, gid=lane>>2, tig=lane&3;
  const int w=tid>>5, tokblk=w>>2, ob=w&3;

#pragma unroll 1
  for(int t=blockIdx.x; t<1024; t+=74){
    const size_t tok0=(size_t)t*128;
    __syncthreads();
    for(int i=tid;i<8192;i+=512){
      int tt=i>>6, k=i&63;
      u32 hi,lo; tf32s(xn[tok0*64+i],hi,lo);
      Xhi[tt*XPAD+k]=hi; Xlo[tt*XPAD+k]=lo;
    }
    __syncthreads();

    float d[2][6][4];
#pragma unroll
    for(int m=0;m<2;m++)
#pragma unroll
      for(int n=0;n<6;n++)
#pragma unroll
        for(int r=0;r<4;r++) d[m][n][r]=0.f;

#pragma unroll
    for(int ks=0;ks<8;ks++){
      u32 ah0[4],al0[4],ah1[4],al1[4];
      {
        const u32* p;
        p = Xhi + (tokblk*32+gid)*XPAD + ks*8 + tig;
        ah0[0]=p[0]; ah0[1]=p[8*XPAD]; ah0[2]=p[4]; ah0[3]=p[8*XPAD+4];
        p = Xlo + (tokblk*32+gid)*XPAD + ks*8 + tig;
        al0[0]=p[0]; al0[1]=p[8*XPAD]; al0[2]=p[4]; al0[3]=p[8*XPAD+4];
        p = Xhi + (tokblk*32+16+gid)*XPAD + ks*8 + tig;
        ah1[0]=p[0]; ah1[1]=p[8*XPAD]; ah1[2]=p[4]; ah1[3]=p[8*XPAD+4];
        p = Xlo + (tokblk*32+16+gid)*XPAD + ks*8 + tig;
        al1[0]=p[0]; al1[1]=p[8*XPAD]; al1[2]=p[4]; al1[3]=p[8*XPAD+4];
      }
#pragma unroll
      for(int n=0;n<6;n++){
        const u32* bh = Whi + (ob*48+n*8+gid)*XPAD + ks*8 + tig;
        u32 bhf[2]={bh[0],bh[4]};
        const u32* bl = Wlo + (ob*48+n*8+gid)*XPAD + ks*8 + tig;
        u32 blf[2]={bl[0],bl[4]};
        mma8(d[0][n],ah0,bhf); mma8(d[0][n],al0,bhf); mma8(d[0][n],ah0,blf);
        mma8(d[1][n],ah1,bhf); mma8(d[1][n],al1,bhf); mma8(d[1][n],ah1,blf);
      }
    }
#pragma unroll
    for(int m=0;m<2;m++){
      int row = tokblk*32+m*16+gid;
#pragma unroll
      for(int n=0;n<6;n++){
        int lc = ob*48+n*8+tig*2;
        int gc = oh*192+lc;
        float2 v0 = make_float2(d[m][n][0]+bs[lc], d[m][n][1]+bs[lc+1]);
        float2 v1 = make_float2(d[m][n][2]+bs[lc], d[m][n][3]+bs[lc+1]);
        *(float2*)(xp + (tok0+row)*384 + gc)   = v0;
        *(float2*)(xp + (tok0+row+8)*384 + gc) = v1;
      }
    }
  }
}

// ============== kernel 3: GRU scan (384 thr, hoisted sigmoids) ==============
__global__ void __launch_bounds__(384,1) k_gru(
  const float* __restrict__ xp, const float* __restrict__ h0,
  const float* __restrict__ w_hh, const float* __restrict__ b_hh,
  float* __restrict__ gru_out, float* __restrict__ out)
{
  __shared__ __align__(16) float hs[128];
  __shared__ float sr[128], sz[128], sxg[128], shg[128];
  const int j=threadIdx.x, b=blockIdx.x;
  u64 w2[64];
  {
    const ulonglong2* wr=(const ulonglong2*)(w_hh+(size_t)j*128);
#pragma unroll
    for(int k=0;k<32;k++){ ulonglong2 v=wr[k]; w2[2*k]=v.x; w2[2*k+1]=v.y; }
  }
  const float bj=b_hh[j];
  if(j<128) hs[j]=h0[b*128+j];
  __syncthreads();
  const float* xbase = xp + (size_t)b*1024*384 + j;
  float* gbase = gru_out + (size_t)b*1024*128;
  const int i = j & 127;
  float xt = xbase[0];
#pragma unroll 1
  for(int t=0;t<1024;t++){
    float xt_n = (t<1023) ? xbase[(size_t)(t+1)*384] : 0.f;
    const ulonglong2* h2=(const ulonglong2*)hs;
    u64 a0=0,a1=0,a2=0,a3=0;
#pragma unroll
    for(int k=0;k<32;k+=2){
      ulonglong2 v0=h2[k], v1=h2[k+1];
      fma2(a0,w2[2*k],v0.x);   fma2(a1,w2[2*k+1],v0.y);
      fma2(a2,w2[2*k+2],v1.x); fma2(a3,w2[2*k+3],v1.y);
    }
    float acc=f2s(add2(add2(a0,a1),add2(a2,a3)));
    // sigmoids hoisted BEFORE the barrier (parallel across all 12 warps)
    if(j<128)       sr[i]=sgm(xt+bj+acc);
    else if(j<256)  sz[i]=sgm(xt+bj+acc);
    else          { shg[i]=bj+acc; sxg[i]=xt; }
    __syncthreads();
    if(j<128){
      float r=sr[i];
      float z=sz[i];
      float g=ftanh(sxg[i]+r*shg[i]);
      float hn=z*(hs[i]-g)+g;           // (1-z)*g + z*h
      gbase[(size_t)t*128+i]=hn;
      hs[i]=hn;
    }
    __syncthreads();
    xt = xt_n;
  }
  if(j<128) out[(size_t)NTOK + (size_t)b*128 + j] = hs[j];
}

// ============== kernel 4a: MLP layer 0 (persistent, 512 thr) ================
#define MPAD 132
#define SML0_WORDS (50688+128)
#define SML0_BYTES (SML0_WORDS*4)
__global__ void __launch_bounds__(512,1) k_l0P(
  const float* __restrict__ gin,
  const float* __restrict__ w0, const float* __restrict__ b0,
  float* __restrict__ f0)
{
  extern __shared__ __align__(16) u32 smw[];
  u32* Whi = smw;
  u32* Wlo = smw + 16896;
  u32* Xhi = smw + 33792;
  u32* Xlo = smw + 42240;
  float* b0s = (float*)(smw + 50688);
  const int tid = threadIdx.x;
  for(int i=tid;i<16384;i+=512){
    int n=i>>7, k=i&127;
    u32 hi,lo; tf32s(w0[i],hi,lo);
    Whi[n*MPAD+k]=hi; Wlo[n*MPAD+k]=lo;
  }
  if(tid<128) b0s[tid]=b0[tid];

  const int lane=tid&31, gid=lane>>2, tig=lane&3;
  const int w=tid>>5, mt=w&3, ob=w>>2;

#pragma unroll 1
  for(int t=blockIdx.x; t<2048; t+=148){
    const size_t tok0=(size_t)t*64;
    __syncthreads();
    for(int i=tid;i<8192;i+=512){
      int tt=i>>7, k=i&127;
      u32 hi,lo; tf32s(gin[tok0*128+i],hi,lo);
      Xhi[tt*MPAD+k]=hi; Xlo[tt*MPAD+k]=lo;
    }
    __syncthreads();

    float d[4][4];
#pragma unroll
    for(int n=0;n<4;n++){ d[n][0]=0;d[n][1]=0;d[n][2]=0;d[n][3]=0; }
#pragma unroll
    for(int ks=0;ks<16;ks++){
      const u32* ph = Xhi + (mt*16+gid)*MPAD + ks*8 + tig;
      u32 ah[4]={ph[0], ph[8*MPAD], ph[4], ph[8*MPAD+4]};
      const u32* pl = Xlo + (mt*16+gid)*MPAD + ks*8 + tig;
      u32 al[4]={pl[0], pl[8*MPAD], pl[4], pl[8*MPAD+4]};
#pragma unroll
      for(int n=0;n<4;n++){
        const u32* bh = Whi + (ob*32+n*8+gid)*MPAD + ks*8 + tig;
        u32 bhf[2]={bh[0],bh[4]};
        const u32* bl = Wlo + (ob*32+n*8+gid)*MPAD + ks*8 + tig;
        u32 blf[2]={bl[0],bl[4]};
        mma8(d[n],ah,bhf); mma8(d[n],al,bhf); mma8(d[n],ah,blf);
      }
    }
    int row = mt*16+gid;
#pragma unroll
    for(int n=0;n<4;n++){
      int col = ob*32+n*8+tig*2;
      float2 v0 = make_float2(lk(d[n][0]+b0s[col]), lk(d[n][1]+b0s[col+1]));
      float2 v1 = make_float2(lk(d[n][2]+b0s[col]), lk(d[n][3]+b0s[col+1]));
      *(float2*)(f0 + (tok0+row)*128 + col)   = v0;
      *(float2*)(f0 + (tok0+row+8)*128 + col) = v1;
    }
  }
}

// ============== kernel 4b: MLP layer 1 + value head (persistent, 512 thr) ===
#define SML1_WORDS (50944+256)
#define SML1_BYTES (SML1_WORDS*4)
__global__ void __launch_bounds__(512,1) k_l1P(
  const float* __restrict__ f0in,
  const float* __restrict__ w1, const float* __restrict__ b1,
  const float* __restrict__ ow, const float* __restrict__ obias,
  float* __restrict__ out)
{
  extern __shared__ __align__(16) u32 smw[];
  u32* Whi = smw;
  u32* Wlo = smw + 16896;
  u32* Xhi = smw + 33792;
  u32* Xlo = smw + 42240;
  float* b1s = (float*)(smw + 50688);
  float* ows = (float*)(smw + 50816);
  float* ppart = (float*)(smw + 50944);   // 256 floats: 4 obs x 64 tokens
  const int tid = threadIdx.x;
  for(int i=tid;i<16384;i+=512){
    int n=i>>7, k=i&127;
    u32 hi,lo; tf32s(w1[i],hi,lo);
    Whi[n*MPAD+k]=hi; Wlo[n*MPAD+k]=lo;
  }
  if(tid<128){ b1s[tid]=b1[tid]; ows[tid]=ow[tid]; }
  const float obv = obias[0];

  const int lane=tid&31, gid=lane>>2, tig=lane&3;
  const int w=tid>>5, mt=w&3, ob=w>>2;

#pragma unroll 1
  for(int t=blockIdx.x; t<2048; t+=148){
    const size_t tok0=(size_t)t*64;
    __syncthreads();
    for(int i=tid;i<8192;i+=512){
      int tt=i>>7, k=i&127;
      u32 hi,lo; tf32s(f0in[tok0*128+i],hi,lo);
      Xhi[tt*MPAD+k]=hi; Xlo[tt*MPAD+k]=lo;
    }
    __syncthreads();

    float d[4][4];
#pragma unroll
    for(int n=0;n<4;n++){ d[n][0]=0;d[n][1]=0;d[n][2]=0;d[n][3]=0; }
#pragma unroll
    for(int ks=0;ks<16;ks++){
      const u32* ph = Xhi + (mt*16+gid)*MPAD + ks*8 + tig;
      u32 ah[4]={ph[0], ph[8*MPAD], ph[4], ph[8*MPAD+4]};
      const u32* pl = Xlo + (mt*16+gid)*MPAD + ks*8 + tig;
      u32 al[4]={pl[0], pl[8*MPAD], pl[4], pl[8*MPAD+4]};
#pragma unroll
      for(int n=0;n<4;n++){
        const u32* bh = Whi + (ob*32+n*8+gid)*MPAD + ks*8 + tig;
        u32 bhf[2]={bh[0],bh[4]};
        const u32* bl = Wlo + (ob*32+n*8+gid)*MPAD + ks*8 + tig;
        u32 blf[2]={bl[0],bl[4]};
        mma8(d[n],ah,bhf); mma8(d[n],al,bhf); mma8(d[n],ah,blf);
      }
    }
    float pA=0.f, pB=0.f;
#pragma unroll
    for(int n=0;n<4;n++){
      int col = ob*32+n*8+tig*2;
      pA += ows[col]*lk(d[n][0]+b1s[col]) + ows[col+1]*lk(d[n][1]+b1s[col+1]);
      pB += ows[col]*lk(d[n][2]+b1s[col]) + ows[col+1]*lk(d[n][3]+b1s[col+1]);
    }
    pA += __shfl_xor_sync(0xFFFFFFFF,pA,1); pA += __shfl_xor_sync(0xFFFFFFFF,pA,2);
    pB += __shfl_xor_sync(0xFFFFFFFF,pB,1); pB += __shfl_xor_sync(0xFFFFFFFF,pB,2);
    if(tig==0){
      ppart[ob*64 + mt*16 + gid]     = pA;
      ppart[ob*64 + mt*16 + gid + 8] = pB;
    }
    __syncthreads();
    if(tid<64)
      out[tok0+tid] = ppart[tid] + ppart[64+tid] + ppart[128+tid] + ppart[192+tid] + obv;
  }
}

// ---------------------------------------------------------------------------
extern "C" void kernel_launch(void* const* d_in, const int* in_sizes, int n_in,
                              void* d_out, int out_size) {
  const float* obs   =(const float*)d_in[0];
  const float* h0    =(const float*)d_in[1];
  const float* me_w1 =(const float*)d_in[2];
  const float* me_b1 =(const float*)d_in[3];
  const float* me_w2 =(const float*)d_in[4];
  const float* me_b2 =(const float*)d_in[5];
  const float* ae_w1 =(const float*)d_in[6];
  const float* ae_b1 =(const float*)d_in[7];
  const float* ae_w2 =(const float*)d_in[8];
  const float* ae_b2 =(const float*)d_in[9];
  const float* in_w  =(const float*)d_in[10];
  const float* in_b  =(const float*)d_in[11];
  const float* wo    =(const float*)d_in[12];
  const float* wob   =(const float*)d_in[13];
  const float* lng   =(const float*)d_in[14];
  const float* lnb   =(const float*)d_in[15];
  const float* w_ih  =(const float*)d_in[16];
  const float* w_hh  =(const float*)d_in[17];
  const float* b_ih  =(const float*)d_in[18];
  const float* b_hh  =(const float*)d_in[19];
  const float* mw0   =(const float*)d_in[20];
  const float* mb0   =(const float*)d_in[21];
  const float* mw1   =(const float*)d_in[22];
  const float* mb1   =(const float*)d_in[23];
  const float* out_w =(const float*)d_in[24];
  const float* out_b =(const float*)d_in[25];
  float* out=(float*)d_out;

  cudaFuncSetAttribute(k_front, cudaFuncAttributeMaxDynamicSharedMemorySize, SM1_BYTES);
  cudaFuncSetAttribute(k_xpP,   cudaFuncAttributeMaxDynamicSharedMemorySize, SM2_BYTES);
  cudaFuncSetAttribute(k_l0P,   cudaFuncAttributeMaxDynamicSharedMemorySize, SML0_BYTES);
  cudaFuncSetAttribute(k_l1P,   cudaFuncAttributeMaxDynamicSharedMemorySize, SML1_BYTES);

  float* xn;  cudaGetSymbolAddress((void**)&xn,  g_xn);
  float* xp;  cudaGetSymbolAddress((void**)&xp,  g_xp);
  float* gr;  cudaGetSymbolAddress((void**)&gr,  g_gru);

  k_front<<<1024,128,SM1_BYTES>>>(obs,me_w1,me_b1,me_w2,me_b2,
                                  ae_w1,ae_b1,ae_w2,ae_b2,
                                  in_w,in_b,wo,wob,lng,lnb,xn);
  k_xpP <<<dim3(74,2),512,SM2_BYTES>>>(xn,w_ih,b_ih,xp);
  k_gru <<<128,384>>>(xp,h0,w_hh,b_hh,gr,out);
  k_l0P <<<148,512,SML0_BYTES>>>(gr,mw0,mb0,xp);       // reuse g_xp as f0
  k_l1P <<<148,512,SML1_BYTES>>>(xp,mw1,mb1,out_w,out_b,out);
}

// round 17
// speedup vs baseline: 1.3364x; 1.0073x over previous
#include <cuda_runtime.h>
#include <math.h>

#define NTOK (128*1024)   // B=128, S=1024
typedef unsigned long long u64;
typedef unsigned int u32;

// ---------------- device scratch (static: no cudaMalloc allowed) ----------
__device__ __align__(128) float g_xn[(size_t)NTOK*64];
__device__ __align__(128) float g_xp[(size_t)NTOK*384];   // xp -> f0
__device__ __align__(128) float g_gru[(size_t)NTOK*128];

// ---------------- f32x2 helpers ---------------------------------------------
__device__ __forceinline__ u64 pk(float lo, float hi){
  u64 r; asm("mov.b64 %0,{%1,%2};" : "=l"(r) : "f"(lo), "f"(hi)); return r;
}
__device__ __forceinline__ void upk(u64 a, float& lo, float& hi){
  asm("mov.b64 {%0,%1},%2;" : "=f"(lo), "=f"(hi) : "l"(a));
}
__device__ __forceinline__ void fma2(u64& d, u64 a, u64 b){
  asm("fma.rn.f32x2 %0,%1,%2,%0;" : "+l"(d) : "l"(a), "l"(b));
}
__device__ __forceinline__ u64 add2(u64 a, u64 b){
  u64 r; asm("add.rn.f32x2 %0,%1,%2;" : "=l"(r) : "l"(a), "l"(b)); return r;
}
__device__ __forceinline__ float f2s(u64 a){
  float lo,hi; upk(a,lo,hi); return lo+hi;
}
__device__ __forceinline__ float lk(float x){ return fmaxf(x, 0.01f*x); }
__device__ __forceinline__ float sgm(float x){ return 1.0f/(1.0f+__expf(-x)); }
__device__ __forceinline__ float ftanh(float x){
  float e=__expf(2.0f*x); return 1.0f - 2.0f/(e+1.0f);
}

// ---------------- tf32 mma helpers ------------------------------------------
__device__ __forceinline__ u32 tf32c(float f){
  u32 r; asm("cvt.rna.tf32.f32 %0,%1;" : "=r"(r) : "f"(f)); return r;
}
__device__ __forceinline__ void tf32s(float f, u32& hi, u32& lo){
  hi = tf32c(f);
  lo = tf32c(f - __uint_as_float(hi));
}
__device__ __forceinline__ void mma8(float* d, const u32* a, const u32* b){
  asm("mma.sync.aligned.m16n8k8.row.col.f32.tf32.tf32.f32 "
      "{%0,%1,%2,%3},{%4,%5,%6,%7},{%8,%9},{%0,%1,%2,%3};"
      : "+f"(d[0]),"+f"(d[1]),"+f"(d[2]),"+f"(d[3])
      : "r"(a[0]),"r"(a[1]),"r"(a[2]),"r"(a[3]),"r"(b[0]),"r"(b[1]));
}

// packed dot products (k_front)
__device__ __forceinline__ float dot32p(const u64* __restrict__ w, const u64 (&x)[16]){
  u64 a0=0,a1=0,a2=0,a3=0;
  const ulonglong2* w2=(const ulonglong2*)w;
#pragma unroll
  for(int k=0;k<4;k++){
    ulonglong2 v0=w2[2*k], v1=w2[2*k+1];
    fma2(a0,v0.x,x[4*k]);   fma2(a1,v0.y,x[4*k+1]);
    fma2(a2,v1.x,x[4*k+2]); fma2(a3,v1.y,x[4*k+3]);
  }
  return f2s(add2(add2(a0,a1),add2(a2,a3)));
}
__device__ __forceinline__ float dot64p(const u64* __restrict__ w, const u64 (&x)[32]){
  u64 a0=0,a1=0,a2=0,a3=0;
  const ulonglong2* w2=(const ulonglong2*)w;
#pragma unroll
  for(int k=0;k<8;k++){
    ulonglong2 v0=w2[2*k], v1=w2[2*k+1];
    fma2(a0,v0.x,x[4*k]);   fma2(a1,v0.y,x[4*k+1]);
    fma2(a2,v1.x,x[4*k+2]); fma2(a3,v1.y,x[4*k+3]);
  }
  return f2s(add2(add2(a0,a1),add2(a2,a3)));
}

// -------- kernel 1 SMEM layout (R6/R9, known-good) ---------------------------
#define OF_MEW1 0
#define OF_MEB1 96
#define OF_MEW2 128
#define OF_MEB2 2176
#define OF_AEW1 2240
#define OF_AEB1 2432
#define OF_AEW2 2464
#define OF_AEB2 4512
#define OF_INW  4576
#define OF_INB  16864
#define OF_WO   17056
#define OF_WOB  21152
#define OF_LNG  21216
#define OF_LNB  21280
#define OF_WTOT 21344
#define OF_BUFA (OF_WTOT)
#define OF_BUFB (OF_WTOT+8192)
#define OF_BUFC (OF_WTOT+16384)
#define OF_BUFD (OF_WTOT+24576)
#define SM1_FLOATS (OF_WTOT+32768)
#define SM1_BYTES  (SM1_FLOATS*4)

__device__ __forceinline__ void enc_m(const float* __restrict__ sm,
                                      u64* __restrict__ buf, int tid,
                                      float x0, float x1, float x2){
  u64 hp[16];
#pragma unroll
  for(int j=0;j<32;j+=2){
    float a0 = sm[OF_MEB1+j]   + sm[OF_MEW1+j*3+0]*x0 + sm[OF_MEW1+j*3+1]*x1 + sm[OF_MEW1+j*3+2]*x2;
    float a1 = sm[OF_MEB1+j+1] + sm[OF_MEW1+j*3+3]*x0 + sm[OF_MEW1+j*3+4]*x1 + sm[OF_MEW1+j*3+5]*x2;
    hp[j>>1]=pk(lk(a0),lk(a1));
  }
#pragma unroll 2
  for(int o=0;o<64;o+=2){
    float y0 = sm[OF_MEB2+o]   + dot32p((const u64*)(sm+OF_MEW2+o*32),hp);
    float y1 = sm[OF_MEB2+o+1] + dot32p((const u64*)(sm+OF_MEW2+(o+1)*32),hp);
    buf[(o>>1)*128+tid]=pk(y0,y1);
  }
}

// ------------- kernel 1: encoders + attention + residual + LayerNorm -------
__global__ void __launch_bounds__(128) k_front(
  const float* __restrict__ obs,
  const float* __restrict__ me_w1, const float* __restrict__ me_b1,
  const float* __restrict__ me_w2, const float* __restrict__ me_b2,
  const float* __restrict__ ae_w1, const float* __restrict__ ae_b1,
  const float* __restrict__ ae_w2, const float* __restrict__ ae_b2,
  const float* __restrict__ in_w,  const float* __restrict__ in_b,
  const float* __restrict__ wo,    const float* __restrict__ wob,
  const float* __restrict__ lng,   const float* __restrict__ lnb,
  float* __restrict__ xn_out)
{
  extern __shared__ __align__(16) float sm[];
  const int tid=threadIdx.x;
  {
    const float* srcs[14]={me_w1,me_b1,me_w2,me_b2,ae_w1,ae_b1,ae_w2,ae_b2,in_w,in_b,wo,wob,lng,lnb};
    const int offs[14]={OF_MEW1,OF_MEB1,OF_MEW2,OF_MEB2,OF_AEW1,OF_AEB1,OF_AEW2,OF_AEB2,OF_INW,OF_INB,OF_WO,OF_WOB,OF_LNG,OF_LNB};
    const int lens[14]={96,32,2048,64,192,32,2048,64,12288,192,4096,64,64,64};
    for(int a=0;a<14;a++)
      for(int i=tid;i<lens[a];i+=128) sm[offs[a]+i]=srcs[a][i];
  }
  __syncthreads();
  u64* bA=(u64*)(sm+OF_BUFA);
  u64* bB=(u64*)(sm+OF_BUFB);
  u64* bC=(u64*)(sm+OF_BUFC);
  u64* bD=(u64*)(sm+OF_BUFD);

  const size_t tok=(size_t)blockIdx.x*128+tid;
  float ob[12];
  {
    const float4* p=(const float4*)(obs+tok*12);
    float4 v0=p[0],v1=p[1],v2=p[2];
    ob[0]=v0.x; ob[1]=v0.y; ob[2]=v0.z; ob[3]=v0.w;
    ob[4]=v1.x; ob[5]=v1.y; ob[6]=v1.z; ob[7]=v1.w;
    ob[8]=v2.x; ob[9]=v2.y; ob[10]=v2.z; ob[11]=v2.w;
  }

  // ---- ace -> bA
  {
    u64 hp[16];
#pragma unroll
    for(int j=0;j<32;j+=2){
      float a0=sm[OF_AEB1+j], a1=sm[OF_AEB1+j+1];
#pragma unroll
      for(int i=0;i<6;i++){ a0+=sm[OF_AEW1+j*6+i]*ob[6+i]; a1+=sm[OF_AEW1+(j+1)*6+i]*ob[6+i]; }
      hp[j>>1]=pk(lk(a0),lk(a1));
    }
#pragma unroll 2
    for(int o=0;o<64;o+=2){
      float y0=sm[OF_AEB2+o]  +dot32p((const u64*)(sm+OF_AEW2+o*32),hp);
      float y1=sm[OF_AEB2+o+1]+dot32p((const u64*)(sm+OF_AEW2+(o+1)*32),hp);
      bA[(o>>1)*128+tid]=pk(y0,y1);
    }
  }
  // ---- q = Wq@ace + bq -> bB
  {
    u64 ar[32];
#pragma unroll
    for(int k=0;k<32;k++) ar[k]=bA[k*128+tid];
#pragma unroll 2
    for(int o=0;o<64;o+=2){
      float y0=sm[OF_INB+o]  +dot64p((const u64*)(sm+OF_INW+(size_t)o*64),ar);
      float y1=sm[OF_INB+o+1]+dot64p((const u64*)(sm+OF_INW+(size_t)(o+1)*64),ar);
      bB[(o>>1)*128+tid]=pk(y0,y1);
    }
  }
  enc_m(sm,bC,tid,ob[0],ob[1],ob[2]);
  enc_m(sm,bD,tid,ob[3],ob[4],ob[5]);

  float a0h[4];
  {
    u64 er[32];
#pragma unroll
    for(int k=0;k<32;k++) er[k]=bC[k*128+tid];
    float s0[4];
#pragma unroll
    for(int h=0;h<4;h++){
      float acc=0.f;
#pragma unroll 2
      for(int oo=0;oo<16;oo+=2){ int o=h*16+oo;
        float q0,q1; upk(bB[(o>>1)*128+tid],q0,q1);
        float k0=sm[OF_INB+64+o]  +dot64p((const u64*)(sm+OF_INW+(size_t)(64+o)*64),er);
        float k1=sm[OF_INB+64+o+1]+dot64p((const u64*)(sm+OF_INW+(size_t)(65+o)*64),er);
        acc+=q0*k0+q1*k1;
      }
      s0[h]=acc;
    }
#pragma unroll
    for(int k=0;k<32;k++) er[k]=bD[k*128+tid];
#pragma unroll
    for(int h=0;h<4;h++){
      float acc=0.f;
#pragma unroll 2
      for(int oo=0;oo<16;oo+=2){ int o=h*16+oo;
        float q0,q1; upk(bB[(o>>1)*128+tid],q0,q1);
        float k0=sm[OF_INB+64+o]  +dot64p((const u64*)(sm+OF_INW+(size_t)(64+o)*64),er);
        float k1=sm[OF_INB+64+o+1]+dot64p((const u64*)(sm+OF_INW+(size_t)(65+o)*64),er);
        acc+=q0*k0+q1*k1;
      }
      a0h[h]=sgm((s0[h]-acc)*0.25f);
    }
  }
  {
    u64 m1r[32], m2r[32];
#pragma unroll
    for(int k=0;k<32;k++){ m1r[k]=bC[k*128+tid]; m2r[k]=bD[k*128+tid]; }
#pragma unroll
    for(int h=0;h<4;h++){
      float a0=a0h[h], a1=1.0f-a0h[h];
#pragma unroll 2
      for(int oo=0;oo<16;oo+=2){ int o=h*16+oo;
        const u64* r0=(const u64*)(sm+OF_INW+(size_t)(128+o)*64);
        const u64* r1=(const u64*)(sm+OF_INW+(size_t)(129+o)*64);
        float y0=sm[OF_INB+128+o]  +a0*dot64p(r0,m1r)+a1*dot64p(r0,m2r);
        float y1=sm[OF_INB+128+o+1]+a0*dot64p(r1,m1r)+a1*dot64p(r1,m2r);
        bB[(o>>1)*128+tid]=pk(y0,y1);
      }
    }
  }
  float mu,rs;
  {
    u64 cr[32];
#pragma unroll
    for(int k=0;k<32;k++) cr[k]=bB[k*128+tid];
    float sum=0.f,sq=0.f;
#pragma unroll 2
    for(int o=0;o<64;o+=2){
      float a0v,a1v; upk(bA[(o>>1)*128+tid],a0v,a1v);
      float x0=sm[OF_WOB+o]  +dot64p((const u64*)(sm+OF_WO+(size_t)o*64),cr)+a0v;
      float x1=sm[OF_WOB+o+1]+dot64p((const u64*)(sm+OF_WO+(size_t)(o+1)*64),cr)+a1v;
      bC[(o>>1)*128+tid]=pk(x0,x1);
      sum+=x0+x1; sq+=x0*x0+x1*x1;
    }
    mu=sum*(1.0f/64.0f);
    float var=sq*(1.0f/64.0f)-mu*mu;
    rs=rsqrtf(var+1e-5f);
  }
  float* op = xn_out + tok*64;
#pragma unroll 2
  for(int o=0;o<64;o+=4){
    float x0,x1,x2,x3;
    upk(bC[(o>>1)*128+tid],x0,x1);
    upk(bC[((o>>1)+1)*128+tid],x2,x3);
    float4 v;
    v.x=(x0-mu)*rs*sm[OF_LNG+o+0]+sm[OF_LNB+o+0];
    v.y=(x1-mu)*rs*sm[OF_LNG+o+1]+sm[OF_LNB+o+1];
    v.z=(x2-mu)*rs*sm[OF_LNG+o+2]+sm[OF_LNB+o+2];
    v.w=(x3-mu)*rs*sm[OF_LNG+o+3]+sm[OF_LNB+o+3];
    *(float4*)(op+o)=v;
  }
}

// ============== kernel 2: xp GEMM (persistent split-tf32, 512 thr) ==========
#define XPAD 68
#define SM2_WORDS (43520+192)
#define SM2_BYTES (SM2_WORDS*4)
__global__ void __launch_bounds__(512,1) k_xpP(
  const float* __restrict__ xn, const float* __restrict__ w_ih,
  const float* __restrict__ b_ih, float* __restrict__ xp)
{
  extern __shared__ __align__(16) u32 smw[];
  u32* Whi = smw;
  u32* Wlo = smw + 13056;
  u32* Xhi = smw + 26112;
  u32* Xlo = smw + 34816;
  float* bs = (float*)(smw + 43520);
  const int tid = threadIdx.x;
  const int oh = blockIdx.y;
  for(int i=tid;i<12288;i+=512){
    int n=i>>6, k=i&63;
    u32 hi,lo; tf32s(w_ih[(size_t)(oh*192+n)*64+k],hi,lo);
    Whi[n*XPAD+k]=hi; Wlo[n*XPAD+k]=lo;
  }
  for(int i=tid;i<192;i+=512) bs[i]=b_ih[oh*192+i];

  const int lane=tid&31, gid=lane>>2, tig=lane&3;
  const int w=tid>>5, tokblk=w>>2, ob=w&3;

#pragma unroll 1
  for(int t=blockIdx.x; t<1024; t+=74){
    const size_t tok0=(size_t)t*128;
    __syncthreads();
    for(int i=tid;i<8192;i+=512){
      int tt=i>>6, k=i&63;
      u32 hi,lo; tf32s(xn[tok0*64+i],hi,lo);
      Xhi[tt*XPAD+k]=hi; Xlo[tt*XPAD+k]=lo;
    }
    __syncthreads();

    float d[2][6][4];
#pragma unroll
    for(int m=0;m<2;m++)
#pragma unroll
      for(int n=0;n<6;n++)
#pragma unroll
        for(int r=0;r<4;r++) d[m][n][r]=0.f;

#pragma unroll
    for(int ks=0;ks<8;ks++){
      u32 ah0[4],al0[4],ah1[4],al1[4];
      {
        const u32* p;
        p = Xhi + (tokblk*32+gid)*XPAD + ks*8 + tig;
        ah0[0]=p[0]; ah0[1]=p[8*XPAD]; ah0[2]=p[4]; ah0[3]=p[8*XPAD+4];
        p = Xlo + (tokblk*32+gid)*XPAD + ks*8 + tig;
        al0[0]=p[0]; al0[1]=p[8*XPAD]; al0[2]=p[4]; al0[3]=p[8*XPAD+4];
        p = Xhi + (tokblk*32+16+gid)*XPAD + ks*8 + tig;
        ah1[0]=p[0]; ah1[1]=p[8*XPAD]; ah1[2]=p[4]; ah1[3]=p[8*XPAD+4];
        p = Xlo + (tokblk*32+16+gid)*XPAD + ks*8 + tig;
        al1[0]=p[0]; al1[1]=p[8*XPAD]; al1[2]=p[4]; al1[3]=p[8*XPAD+4];
      }
#pragma unroll
      for(int n=0;n<6;n++){
        const u32* bh = Whi + (ob*48+n*8+gid)*XPAD + ks*8 + tig;
        u32 bhf[2]={bh[0],bh[4]};
        const u32* bl = Wlo + (ob*48+n*8+gid)*XPAD + ks*8 + tig;
        u32 blf[2]={bl[0],bl[4]};
        mma8(d[0][n],ah0,bhf); mma8(d[0][n],al0,bhf); mma8(d[0][n],ah0,blf);
        mma8(d[1][n],ah1,bhf); mma8(d[1][n],al1,bhf); mma8(d[1][n],ah1,blf);
      }
    }
#pragma unroll
    for(int m=0;m<2;m++){
      int row = tokblk*32+m*16+gid;
#pragma unroll
      for(int n=0;n<6;n++){
        int lc = ob*48+n*8+tig*2;
        int gc = oh*192+lc;
        float2 v0 = make_float2(d[m][n][0]+bs[lc], d[m][n][1]+bs[lc+1]);
        float2 v1 = make_float2(d[m][n][2]+bs[lc], d[m][n][3]+bs[lc+1]);
        *(float2*)(xp + (tok0+row)*384 + gc)   = v0;
        *(float2*)(xp + (tok0+row+8)*384 + gc) = v1;
      }
    }
  }
}

// ============== kernel 3: GRU scan (384 thr, hoisted sigmoids) ==============
__global__ void __launch_bounds__(384,1) k_gru(
  const float* __restrict__ xp, const float* __restrict__ h0,
  const float* __restrict__ w_hh, const float* __restrict__ b_hh,
  float* __restrict__ gru_out, float* __restrict__ out)
{
  __shared__ __align__(16) float hs[128];
  __shared__ float sr[128], sz[128], sxg[128], shg[128];
  const int j=threadIdx.x, b=blockIdx.x;
  u64 w2[64];
  {
    const ulonglong2* wr=(const ulonglong2*)(w_hh+(size_t)j*128);
#pragma unroll
    for(int k=0;k<32;k++){ ulonglong2 v=wr[k]; w2[2*k]=v.x; w2[2*k+1]=v.y; }
  }
  const float bj=b_hh[j];
  if(j<128) hs[j]=h0[b*128+j];
  __syncthreads();
  const float* xbase = xp + (size_t)b*1024*384 + j;
  float* gbase = gru_out + (size_t)b*1024*128;
  const int i = j & 127;
  float xt = xbase[0];
#pragma unroll 1
  for(int t=0;t<1024;t++){
    float xt_n = (t<1023) ? xbase[(size_t)(t+1)*384] : 0.f;
    const ulonglong2* h2=(const ulonglong2*)hs;
    u64 a0=0,a1=0,a2=0,a3=0;
#pragma unroll
    for(int k=0;k<32;k+=2){
      ulonglong2 v0=h2[k], v1=h2[k+1];
      fma2(a0,w2[2*k],v0.x);   fma2(a1,w2[2*k+1],v0.y);
      fma2(a2,w2[2*k+2],v1.x); fma2(a3,w2[2*k+3],v1.y);
    }
    float acc=f2s(add2(add2(a0,a1),add2(a2,a3)));
    if(j<128)       sr[i]=sgm(xt+bj+acc);
    else if(j<256)  sz[i]=sgm(xt+bj+acc);
    else          { shg[i]=bj+acc; sxg[i]=xt; }
    __syncthreads();
    if(j<128){
      float r=sr[i];
      float z=sz[i];
      float g=ftanh(sxg[i]+r*shg[i]);
      float hn=z*(hs[i]-g)+g;
      gbase[(size_t)t*128+i]=hn;
      hs[i]=hn;
    }
    __syncthreads();
    xt = xt_n;
  }
  if(j<128) out[(size_t)NTOK + (size_t)b*128 + j] = hs[j];
}

// ============== kernel 4a: MLP layer 0 (persistent, 512 thr) ================
#define MPAD 132
#define SML0_WORDS (50688+128)
#define SML0_BYTES (SML0_WORDS*4)
__global__ void __launch_bounds__(512,1) k_l0P(
  const float* __restrict__ gin,
  const float* __restrict__ w0, const float* __restrict__ b0,
  float* __restrict__ f0)
{
  extern __shared__ __align__(16) u32 smw[];
  u32* Whi = smw;
  u32* Wlo = smw + 16896;
  u32* Xhi = smw + 33792;
  u32* Xlo = smw + 42240;
  float* b0s = (float*)(smw + 50688);
  const int tid = threadIdx.x;
  for(int i=tid;i<16384;i+=512){
    int n=i>>7, k=i&127;
    u32 hi,lo; tf32s(w0[i],hi,lo);
    Whi[n*MPAD+k]=hi; Wlo[n*MPAD+k]=lo;
  }
  if(tid<128) b0s[tid]=b0[tid];

  const int lane=tid&31, gid=lane>>2, tig=lane&3;
  const int w=tid>>5, mt=w&3, ob=w>>2;

#pragma unroll 1
  for(int t=blockIdx.x; t<2048; t+=148){
    const size_t tok0=(size_t)t*64;
    __syncthreads();
    for(int i=tid;i<8192;i+=512){
      int tt=i>>7, k=i&127;
      u32 hi,lo; tf32s(gin[tok0*128+i],hi,lo);
      Xhi[tt*MPAD+k]=hi; Xlo[tt*MPAD+k]=lo;
    }
    __syncthreads();

    float d[4][4];
#pragma unroll
    for(int n=0;n<4;n++){ d[n][0]=0;d[n][1]=0;d[n][2]=0;d[n][3]=0; }
#pragma unroll
    for(int ks=0;ks<16;ks++){
      const u32* ph = Xhi + (mt*16+gid)*MPAD + ks*8 + tig;
      u32 ah[4]={ph[0], ph[8*MPAD], ph[4], ph[8*MPAD+4]};
      const u32* pl = Xlo + (mt*16+gid)*MPAD + ks*8 + tig;
      u32 al[4]={pl[0], pl[8*MPAD], pl[4], pl[8*MPAD+4]};
#pragma unroll
      for(int n=0;n<4;n++){
        const u32* bh = Whi + (ob*32+n*8+gid)*MPAD + ks*8 + tig;
        u32 bhf[2]={bh[0],bh[4]};
        const u32* bl = Wlo + (ob*32+n*8+gid)*MPAD + ks*8 + tig;
        u32 blf[2]={bl[0],bl[4]};
        mma8(d[n],ah,bhf); mma8(d[n],al,bhf); mma8(d[n],ah,blf);
      }
    }
    int row = mt*16+gid;
#pragma unroll
    for(int n=0;n<4;n++){
      int col = ob*32+n*8+tig*2;
      float2 v0 = make_float2(lk(d[n][0]+b0s[col]), lk(d[n][1]+b0s[col+1]));
      float2 v1 = make_float2(lk(d[n][2]+b0s[col]), lk(d[n][3]+b0s[col+1]));
      *(float2*)(f0 + (tok0+row)*128 + col)   = v0;
      *(float2*)(f0 + (tok0+row+8)*128 + col) = v1;
    }
  }
}

// ============== kernel 4b: MLP layer 1 + value head (persistent, 512 thr) ===
#define SML1_WORDS (50944+256)
#define SML1_BYTES (SML1_WORDS*4)
__global__ void __launch_bounds__(512,1) k_l1P(
  const float* __restrict__ f0in,
  const float* __restrict__ w1, const float* __restrict__ b1,
  const float* __restrict__ ow, const float* __restrict__ obias,
  float* __restrict__ out)
{
  extern __shared__ __align__(16) u32 smw[];
  u32* Whi = smw;
  u32* Wlo = smw + 16896;
  u32* Xhi = smw + 33792;
  u32* Xlo = smw + 42240;
  float* b1s = (float*)(smw + 50688);
  float* ows = (float*)(smw + 50816);
  float* ppart = (float*)(smw + 50944);
  const int tid = threadIdx.x;
  for(int i=tid;i<16384;i+=512){
    int n=i>>7, k=i&127;
    u32 hi,lo; tf32s(w1[i],hi,lo);
    Whi[n*MPAD+k]=hi; Wlo[n*MPAD+k]=lo;
  }
  if(tid<128){ b1s[tid]=b1[tid]; ows[tid]=ow[tid]; }
  const float obv = obias[0];

  const int lane=tid&31, gid=lane>>2, tig=lane&3;
  const int w=tid>>5, mt=w&3, ob=w>>2;

#pragma unroll 1
  for(int t=blockIdx.x; t<2048; t+=148){
    const size_t tok0=(size_t)t*64;
    __syncthreads();
    for(int i=tid;i<8192;i+=512){
      int tt=i>>7, k=i&127;
      u32 hi,lo; tf32s(f0in[tok0*128+i],hi,lo);
      Xhi[tt*MPAD+k]=hi; Xlo[tt*MPAD+k]=lo;
    }
    __syncthreads();

    float d[4][4];
#pragma unroll
    for(int n=0;n<4;n++){ d[n][0]=0;d[n][1]=0;d[n][2]=0;d[n][3]=0; }
#pragma unroll
    for(int ks=0;ks<16;ks++){
      const u32* ph = Xhi + (mt*16+gid)*MPAD + ks*8 + tig;
      u32 ah[4]={ph[0], ph[8*MPAD], ph[4], ph[8*MPAD+4]};
      const u32* pl = Xlo + (mt*16+gid)*MPAD + ks*8 + tig;
      u32 al[4]={pl[0], pl[8*MPAD], pl[4], pl[8*MPAD+4]};
#pragma unroll
      for(int n=0;n<4;n++){
        const u32* bh = Whi + (ob*32+n*8+gid)*MPAD + ks*8 + tig;
        u32 bhf[2]={bh[0],bh[4]};
        const u32* bl = Wlo + (ob*32+n*8+gid)*MPAD + ks*8 + tig;
        u32 blf[2]={bl[0],bl[4]};
        mma8(d[n],ah,bhf); mma8(d[n],al,bhf); mma8(d[n],ah,blf);
      }
    }
    float pA=0.f, pB=0.f;
#pragma unroll
    for(int n=0;n<4;n++){
      int col = ob*32+n*8+tig*2;
      pA += ows[col]*lk(d[n][0]+b1s[col]) + ows[col+1]*lk(d[n][1]+b1s[col+1]);
      pB += ows[col]*lk(d[n][2]+b1s[col]) + ows[col+1]*lk(d[n][3]+b1s[col+1]);
    }
    pA += __shfl_xor_sync(0xFFFFFFFF,pA,1); pA += __shfl_xor_sync(0xFFFFFFFF,pA,2);
    pB += __shfl_xor_sync(0xFFFFFFFF,pB,1); pB += __shfl_xor_sync(0xFFFFFFFF,pB,2);
    if(tig==0){
      ppart[ob*64 + mt*16 + gid]     = pA;
      ppart[ob*64 + mt*16 + gid + 8] = pB;
    }
    __syncthreads();
    if(tid<64)
      out[tok0+tid] = ppart[tid] + ppart[64+tid] + ppart[128+tid] + ppart[192+tid] + obv;
  }
}

// ---------------------------------------------------------------------------
extern "C" void kernel_launch(void* const* d_in, const int* in_sizes, int n_in,
                              void* d_out, int out_size) {
  const float* obs   =(const float*)d_in[0];
  const float* h0    =(const float*)d_in[1];
  const float* me_w1 =(const float*)d_in[2];
  const float* me_b1 =(const float*)d_in[3];
  const float* me_w2 =(const float*)d_in[4];
  const float* me_b2 =(const float*)d_in[5];
  const float* ae_w1 =(const float*)d_in[6];
  const float* ae_b1 =(const float*)d_in[7];
  const float* ae_w2 =(const float*)d_in[8];
  const float* ae_b2 =(const float*)d_in[9];
  const float* in_w  =(const float*)d_in[10];
  const float* in_b  =(const float*)d_in[11];
  const float* wo    =(const float*)d_in[12];
  const float* wob   =(const float*)d_in[13];
  const float* lng   =(const float*)d_in[14];
  const float* lnb   =(const float*)d_in[15];
  const float* w_ih  =(const float*)d_in[16];
  const float* w_hh  =(const float*)d_in[17];
  const float* b_ih  =(const float*)d_in[18];
  const float* b_hh  =(const float*)d_in[19];
  const float* mw0   =(const float*)d_in[20];
  const float* mb0   =(const float*)d_in[21];
  const float* mw1   =(const float*)d_in[22];
  const float* mb1   =(const float*)d_in[23];
  const float* out_w =(const float*)d_in[24];
  const float* out_b =(const float*)d_in[25];
  float* out=(float*)d_out;

  cudaFuncSetAttribute(k_front, cudaFuncAttributeMaxDynamicSharedMemorySize, SM1_BYTES);
  cudaFuncSetAttribute(k_xpP,   cudaFuncAttributeMaxDynamicSharedMemorySize, SM2_BYTES);
  cudaFuncSetAttribute(k_l0P,   cudaFuncAttributeMaxDynamicSharedMemorySize, SML0_BYTES);
  cudaFuncSetAttribute(k_l1P,   cudaFuncAttributeMaxDynamicSharedMemorySize, SML1_BYTES);

  float* xn;  cudaGetSymbolAddress((void**)&xn,  g_xn);
  float* xp;  cudaGetSymbolAddress((void**)&xp,  g_xp);
  float* gr;  cudaGetSymbolAddress((void**)&gr,  g_gru);

  k_front<<<1024,128,SM1_BYTES>>>(obs,me_w1,me_b1,me_w2,me_b2,
                                  ae_w1,ae_b1,ae_w2,ae_b2,
                                  in_w,in_b,wo,wob,lng,lnb,xn);
  k_xpP <<<dim3(74,2),512,SM2_BYTES>>>(xn,w_ih,b_ih,xp);
  k_gru <<<128,384>>>(xp,h0,w_hh,b_hh,gr,out);
  k_l0P <<<148,512,SML0_BYTES>>>(gr,mw0,mb0,xp);       // reuse g_xp as f0
  k_l1P <<<148,512,SML1_BYTES>>>(xp,mw1,mb1,out_w,out_b,out);
}